// round 13
// baseline (speedup 1.0000x reference)
#include <cuda_runtime.h>
#include <cuda_fp16.h>
#include <cstdint>

#define T_LEN   12
#define N_HEADS 8
#define N_NODES 16384
#define H_DIM   64
#define G_DIM   256
#define NB      32           // nodes per CTA (= GEMM M)
#define THREADS 512

// ---- LSTM shared memory layout (bytes) ----
#define SA0     0            // A tile buf0: [32 rows][128 k] fp16 swizzled (8192)
#define SA1     8192         // A tile buf1                                  (8192)
#define SBSTG   16384        // B staging chunk: [64 rows][128 k] fp16      (16384)
#define SBIAS   32768        // bias fp32 [256]                             (1024)
#define SMEM_TOTAL 33792

// Scratch
__device__ __half g_x16[(size_t)T_LEN * N_NODES * H_DIM];            // x in fp16
__device__ __half g_hs0[(size_t)N_HEADS * T_LEN * N_NODES * H_DIM];  // layer-0 h
__device__ __half g_hs1[(size_t)N_HEADS * T_LEN * N_NODES * H_DIM];  // layer-1 h

__device__ __forceinline__ uint32_t swzoff(int R8, int row, int k) {
    uint32_t off = (uint32_t)((((row >> 3) + (k >> 6) * R8) << 10)
                 + ((row & 7) << 7) + ((k & 63) << 1));
    return off ^ ((off >> 3) & 0x70);
}

__device__ __forceinline__ uint32_t smem_u32(const void* p) {
    uint32_t a;
    asm("{ .reg .u64 t; cvta.to.shared.u64 t, %1; cvt.u32.u64 %0, t; }" : "=r"(a) : "l"(p));
    return a;
}

__device__ __forceinline__ void ldsm4(uint32_t* r, uint32_t addr) {
    asm volatile("ldmatrix.sync.aligned.m8n8.x4.shared.b16 {%0,%1,%2,%3}, [%4];"
        : "=r"(r[0]), "=r"(r[1]), "=r"(r[2]), "=r"(r[3]) : "r"(addr));
}

__device__ __forceinline__ void mma_f16(float* c, const uint32_t* a,
                                        uint32_t b0, uint32_t b1) {
    asm volatile("mma.sync.aligned.m16n8k16.row.col.f32.f16.f16.f32 "
        "{%0,%1,%2,%3}, {%4,%5,%6,%7}, {%8,%9}, {%0,%1,%2,%3};"
        : "+f"(c[0]), "+f"(c[1]), "+f"(c[2]), "+f"(c[3])
        : "r"(a[0]), "r"(a[1]), "r"(a[2]), "r"(a[3]), "r"(b0), "r"(b1));
}

__device__ __forceinline__ float tanha(float x) {
    float y;
    asm("tanh.approx.f32 %0, %1;" : "=f"(y) : "f"(x));
    return y;
}
__device__ __forceinline__ float siga(float x) {
    return fmaf(tanha(0.5f * x), 0.5f, 0.5f);
}
__device__ __forceinline__ float2 tanh2(float a, float b) {
    __half2 hx = __floats2half2_rn(a, b);
    uint32_t xr = *(uint32_t*)&hx, yr;
    asm("tanh.approx.f16x2 %0, %1;" : "=r"(yr) : "r"(xr));
    return __half22float2(*(__half2*)&yr);
}
__device__ __forceinline__ float2 sig2(float a, float b) {
    float2 t = tanh2(0.5f * a, 0.5f * b);
    return make_float2(fmaf(t.x, 0.5f, 0.5f), fmaf(t.y, 0.5f, 0.5f));
}

#define CP_ASYNC16(dst_u32, src) \
    asm volatile("cp.async.ca.shared.global [%0], [%1], 16;" :: "r"(dst_u32), "l"(src) : "memory")
#define CP_COMMIT() asm volatile("cp.async.commit_group;" ::: "memory")
#define CP_WAIT0()  asm volatile("cp.async.wait_group 0;" ::: "memory")

// 8 fp32 -> 8 fp16, one 16B store into swizzled tile
__device__ __forceinline__ void cvt8_store_f16(const float* v, char* smem,
                                               int tile, uint32_t off) {
    uint32_t w[4];
    #pragma unroll
    for (int qq = 0; qq < 4; ++qq) {
        __half2 h = __floats2half2_rn(v[2 * qq], v[2 * qq + 1]);
        w[qq] = *(uint32_t*)&h;
    }
    *(uint4*)(smem + tile + off) = make_uint4(w[0], w[1], w[2], w[3]);
}

// x fp32 -> fp16 (one-time)
__global__ __launch_bounds__(256)
void x_convert_kernel(const float* __restrict__ x)
{
    size_t i8 = ((size_t)blockIdx.x * 256 + threadIdx.x) * 8;
    float4 v0 = *(const float4*)(x + i8);
    float4 v1 = *(const float4*)(x + i8 + 4);
    __half2 h0 = __floats2half2_rn(v0.x, v0.y);
    __half2 h1 = __floats2half2_rn(v0.z, v0.w);
    __half2 h2 = __floats2half2_rn(v1.x, v1.y);
    __half2 h3 = __floats2half2_rn(v1.z, v1.w);
    *(uint4*)(g_x16 + i8) = make_uint4(*(uint32_t*)&h0, *(uint32_t*)&h1,
                                       *(uint32_t*)&h2, *(uint32_t*)&h3);
}

__global__ __launch_bounds__(THREADS, 3)
void lstm_mma_kernel(const float* __restrict__ W_ih,
                     const float* __restrict__ W_hh,
                     const float* __restrict__ b_ih,
                     const float* __restrict__ b_hh,
                     const float* __restrict__ h0,
                     const float* __restrict__ c0)
{
    extern __shared__ char smem[];
    const uint32_t sbase = smem_u32(smem);
    float* sbias = (float*)(smem + SBIAS);

    const int tid  = threadIdx.x;
    const int warp = tid >> 5;          // wn: N-warp (16), 16 gate-rows each
    const int lane = tid & 31;
    const int wn   = warp;
    const int gid  = lane >> 2;
    const int q    = lane & 3;
    const int jhd  = wn * 4 + q;        // this thread's single hd

    const int a_row_lane = ((lane >> 3) & 1) * 8 + (lane & 7);
    const int a_kadd     = (lane >> 4) * 8;
    const int b_row_lane = (lane >> 4) * 8 + (lane & 7);
    const int b_kadd     = ((lane >> 3) & 1) * 8;

    const int head  = blockIdx.y;
    const int node0 = blockIdx.x * NB;

    // per-thread x staging chunk (256 chunks of 16B cover the x-region)
    const int stg_n = (tid & 255) >> 3;
    const int stg_k = (tid & 7) * 8;
    const bool stg_on = (tid < 256);

    float c_reg[2][2];      // [mtile][rowhalf], 1 hd each

    for (int l = 0; l < 2; ++l) {
        // ======== layer prologue ========
        const float* Wih_g = W_ih + (size_t)(l * N_HEADS + head) * (G_DIM * H_DIM);
        const float* Whh_g = W_hh + (size_t)(l * N_HEADS + head) * (G_DIM * H_DIM);

        // bias
        if (tid < 256) {
            const float* bi = b_ih + (size_t)(l * N_HEADS + head) * G_DIM;
            const float* bh = b_hh + (size_t)(l * N_HEADS + head) * G_DIM;
            sbias[tid] = bi[tid] + bh[tid];
        }
        // h0 -> A[0] h-region (k 64..127), fp32 -> fp16 (256 groups)
        if (tid < 256) {
            const float* hsrc = h0 + ((size_t)(head * 2 + l) * N_NODES + node0) * H_DIM;
            int n  = tid >> 3;
            int k8 = (tid & 7) * 8;
            float v[8];
            float4 v0 = *(const float4*)(hsrc + n * 64 + k8);
            float4 v1 = *(const float4*)(hsrc + n * 64 + k8 + 4);
            v[0]=v0.x; v[1]=v0.y; v[2]=v0.z; v[3]=v0.w;
            v[4]=v1.x; v[5]=v1.y; v[6]=v1.z; v[7]=v1.w;
            cvt8_store_f16(v, smem, SA0, swzoff(4, n, 64 + k8));
        }
        // c0 -> registers (1 hd per cell)
        {
            const float* cbase = c0 + ((size_t)(head * 2 + l) * N_NODES + node0) * H_DIM;
            #pragma unroll
            for (int mt = 0; mt < 2; ++mt)
                #pragma unroll
                for (int rh = 0; rh < 2; ++rh)
                    c_reg[mt][rh] = cbase[(size_t)(mt * 16 + gid + rh * 8) * 64 + jhd];
        }

        // ---- B: stage 4 chunks of 64 rows through SBSTG, hoist to registers ----
        // global permuted row: row = (wn<<4)|(hf<<3)|(q<<1)|b ; g=(hf<<1)|b ; j=(wn<<2)|q
        uint32_t bfr[8][4];
        #pragma unroll 1
        for (int ch = 0; ch < 4; ++ch) {
            #pragma unroll
            for (int i = 0; i < 2; ++i) {
                int gidx = tid + i * THREADS;      // 1024 groups: 64 rows x 16 k8
                int rloc = gidx >> 4;
                int k8   = (gidx & 15) * 8;
                int row_out = ch * 64 + rloc;
                int wn_ = row_out >> 4;
                int hf_ = (row_out >> 3) & 1;
                int q_  = (row_out >> 1) & 3;
                int b_  = row_out & 1;
                int g   = (hf_ << 1) | b_;
                int jj  = (wn_ << 2) | q_;
                const float* src = (k8 < 64) ? (Wih_g + (g * 64 + jj) * 64 + k8)
                                             : (Whh_g + (g * 64 + jj) * 64 + (k8 - 64));
                float v[8];
                float4 v0 = *(const float4*)(src);
                float4 v1 = *(const float4*)(src + 4);
                v[0]=v0.x; v[1]=v0.y; v[2]=v0.z; v[3]=v0.w;
                v[4]=v1.x; v[5]=v1.y; v[6]=v1.z; v[7]=v1.w;
                cvt8_store_f16(v, smem, SBSTG, swzoff(8, rloc, k8));
            }
            __syncthreads();
            if ((wn >> 2) == ch) {
                int rbase = (wn & 3) * 16;
                #pragma unroll
                for (int kc = 0; kc < 8; ++kc) {
                    uint32_t off = swzoff(8, rbase + b_row_lane, kc * 16 + b_kadd);
                    ldsm4(bfr[kc], sbase + SBSTG + off);
                }
            }
            __syncthreads();
        }
        // hoist biases: bias_r[hf][b] for gate g=(hf<<1)|b at hd jhd
        float bias_r[2][2];
        #pragma unroll
        for (int hf = 0; hf < 2; ++hf)
            #pragma unroll
            for (int b = 0; b < 2; ++b)
                bias_r[hf][b] = sbias[(((hf << 1) | b) * 64) + jhd];

        // fp16 input stream for this layer
        const __half* in16 = (l == 0)
            ? (g_x16 + (size_t)node0 * H_DIM)
            : (g_hs0 + ((size_t)head * T_LEN * N_NODES + node0) * H_DIM);
        __half* out_base = ((l == 0) ? g_hs0 : g_hs1)
                         + (size_t)head * T_LEN * N_NODES * H_DIM;

        // x_0 -> A[0] x-region via cp.async
        if (stg_on)
            CP_ASYNC16(sbase + SA0 + swzoff(4, stg_n, stg_k), in16 + stg_n * 64 + stg_k);
        CP_COMMIT(); CP_WAIT0();
        __syncthreads();

        // ======== scan (double-buffered A, ONE sync per step) ========
        for (int t = 0; t < T_LEN; ++t) {
            const int SAc = (t & 1) ? SA1 : SA0;
            const int SAn = (t & 1) ? SA0 : SA1;
            const bool notlast = (t + 1 < T_LEN);

            // stage x_{t+1} into A[nxt] x-region via cp.async (overlaps MMA)
            if (notlast && stg_on) {
                const __half* srcn = in16 + (size_t)(t + 1) * N_NODES * H_DIM;
                CP_ASYNC16(sbase + SAn + swzoff(4, stg_n, stg_k), srcn + stg_n * 64 + stg_k);
                CP_COMMIT();
            }

            // accum, bias-initialized: acc[mt][hf][rh*2+b]
            float acc[2][2][4];
            #pragma unroll
            for (int mt = 0; mt < 2; ++mt)
                #pragma unroll
                for (int hf = 0; hf < 2; ++hf) {
                    acc[mt][hf][0] = bias_r[hf][0]; acc[mt][hf][1] = bias_r[hf][1];
                    acc[mt][hf][2] = bias_r[hf][0]; acc[mt][hf][3] = bias_r[hf][1];
                }

            // MMA: A from SMEM, B fully register-resident (warp's 16 gate-rows)
            #pragma unroll
            for (int kc = 0; kc < 8; ++kc) {
                int k0 = kc * 16;
                uint32_t af[2][4];
                #pragma unroll
                for (int mt = 0; mt < 2; ++mt) {
                    uint32_t off = swzoff(4, mt * 16 + a_row_lane, k0 + a_kadd);
                    ldsm4(af[mt], sbase + SAc + off);
                }
                #pragma unroll
                for (int hf = 0; hf < 2; ++hf)
                    #pragma unroll
                    for (int mt = 0; mt < 2; ++mt)
                        mma_f16(acc[mt][hf], af[mt], bfr[kc][hf*2], bfr[kc][hf*2+1]);
            }

            // epilogue: 4 cells (mt x rh), 1 hd each; all 4 gates thread-local
            #pragma unroll
            for (int mt = 0; mt < 2; ++mt) {
                float iv0 = acc[mt][0][0], fv0 = acc[mt][0][1];
                float gv0 = acc[mt][1][0], ov0 = acc[mt][1][1];
                float iv1 = acc[mt][0][2], fv1 = acc[mt][0][3];
                float gv1 = acc[mt][1][2], ov1 = acc[mt][1][3];

                float2 tg = tanh2(gv0, gv1);
                float2 si = sig2(iv0, iv1);
                float cc0 = siga(fv0) * c_reg[mt][0] + si.x * tg.x;
                float cc1 = siga(fv1) * c_reg[mt][1] + si.y * tg.y;
                c_reg[mt][0] = cc0; c_reg[mt][1] = cc1;
                float2 tc = tanh2(cc0, cc1);
                float2 so = sig2(ov0, ov1);
                __half hv0 = __float2half_rn(so.x * tc.x);
                __half hv1 = __float2half_rn(so.y * tc.y);

                int r0 = mt * 16 + gid, r1 = r0 + 8;
                out_base[((size_t)t * N_NODES + node0 + r0) * H_DIM + jhd] = hv0;
                out_base[((size_t)t * N_NODES + node0 + r1) * H_DIM + jhd] = hv1;
                if (notlast) {
                    *(__half*)(smem + SAn + swzoff(4, r0, 64 + jhd)) = hv0;
                    *(__half*)(smem + SAn + swzoff(4, r1, 64 + jhd)) = hv1;
                }
            }
            if (notlast) { CP_WAIT0(); }
            __syncthreads();
        }
        __threadfence();   // layer-0 h STGs visible before layer-1 cp.async reads
        __syncthreads();
    }
}

// out[o][n][hd] = sum_c hs1[c][n][hd] * conv_w[o][c] + conv_b[o]
__global__ __launch_bounds__(256)
void conv_kernel(const float* __restrict__ conv_w,
                 const float* __restrict__ conv_b,
                 float* __restrict__ out)
{
    __shared__ float sw[T_LEN * N_HEADS * T_LEN];
    __shared__ float sb[T_LEN];
    for (int i = threadIdx.x; i < T_LEN * N_HEADS * T_LEN; i += 256)
        sw[i] = conv_w[i];
    if (threadIdx.x < T_LEN) sb[threadIdx.x] = conv_b[threadIdx.x];
    __syncthreads();

    const size_t stride = (size_t)N_NODES * H_DIM;
    size_t nh4 = ((size_t)blockIdx.x * 256 + threadIdx.x) * 4;

    float acc[T_LEN][4];
    #pragma unroll
    for (int o = 0; o < T_LEN; ++o) {
        float b = sb[o];
        acc[o][0] = b; acc[o][1] = b; acc[o][2] = b; acc[o][3] = b;
    }
    #pragma unroll 4
    for (int c = 0; c < N_HEADS * T_LEN; ++c) {
        uint2 raw = *(const uint2*)(g_hs1 + (size_t)c * stride + nh4);
        float2 f0 = __half22float2(*(__half2*)&raw.x);
        float2 f1 = __half22float2(*(__half2*)&raw.y);
        #pragma unroll
        for (int o = 0; o < T_LEN; ++o) {
            float w = sw[o * (N_HEADS * T_LEN) + c];
            acc[o][0] += f0.x * w; acc[o][1] += f0.y * w;
            acc[o][2] += f1.x * w; acc[o][3] += f1.y * w;
        }
    }
    #pragma unroll
    for (int o = 0; o < T_LEN; ++o)
        *(float4*)(out + (size_t)o * stride + nh4) =
            make_float4(acc[o][0], acc[o][1], acc[o][2], acc[o][3]);
}

extern "C" void kernel_launch(void* const* d_in, const int* in_sizes, int n_in,
                              void* d_out, int out_size)
{
    const float* x      = (const float*)d_in[0];
    const float* W_ih   = (const float*)d_in[1];
    const float* W_hh   = (const float*)d_in[2];
    const float* b_ih   = (const float*)d_in[3];
    const float* b_hh   = (const float*)d_in[4];
    const float* h0     = (const float*)d_in[5];
    const float* c0     = (const float*)d_in[6];
    const float* conv_w = (const float*)d_in[7];
    const float* conv_b = (const float*)d_in[8];
    float* out = (float*)d_out;

    cudaFuncSetAttribute(lstm_mma_kernel,
                         cudaFuncAttributeMaxDynamicSharedMemorySize, SMEM_TOTAL);

    // x fp32 -> fp16
    x_convert_kernel<<<(T_LEN * N_NODES * H_DIM) / (8 * 256), 256>>>(x);

    dim3 grid(N_NODES / NB, N_HEADS);     // 512 x 8 = 4096 CTAs, 512 thr
    lstm_mma_kernel<<<grid, THREADS, SMEM_TOTAL>>>(W_ih, W_hh, b_ih, b_hh, h0, c0);

    conv_kernel<<<(N_NODES * H_DIM) / (4 * 256), 256>>>(conv_w, conv_b, out);
}

// round 14
// speedup vs baseline: 2.2327x; 2.2327x over previous
#include <cuda_runtime.h>
#include <cuda_fp16.h>
#include <cstdint>

#define T_LEN   12
#define N_HEADS 8
#define N_NODES 16384
#define H_DIM   64
#define G_DIM   256
#define NB      64           // nodes per CTA (= GEMM M)
#define THREADS 256

// ---- LSTM shared memory layout (bytes) ----
#define SA0     0            // A tile buf0: [64 rows][128 k] fp16 swizzled (16384)
#define SA1     16384        // A tile buf1                                  (16384)
#define SB      32768        // B tile: [256 rows][128 k] fp16              (65536)
#define SBIAS   98304        // bias fp32 [256]                             (1024)
#define SMEM_TOTAL 99328

// Scratch
__device__ __half g_x16[(size_t)T_LEN * N_NODES * H_DIM];            // x in fp16
__device__ __half g_hs0[(size_t)N_HEADS * T_LEN * N_NODES * H_DIM];  // layer-0 h
__device__ __half g_hs1[(size_t)N_HEADS * T_LEN * N_NODES * H_DIM];  // layer-1 h

__device__ __forceinline__ uint32_t swzoff(int R8, int row, int k) {
    uint32_t off = (uint32_t)((((row >> 3) + (k >> 6) * R8) << 10)
                 + ((row & 7) << 7) + ((k & 63) << 1));
    return off ^ ((off >> 3) & 0x70);
}

__device__ __forceinline__ uint32_t smem_u32(const void* p) {
    uint32_t a;
    asm("{ .reg .u64 t; cvta.to.shared.u64 t, %1; cvt.u32.u64 %0, t; }" : "=r"(a) : "l"(p));
    return a;
}

__device__ __forceinline__ void ldsm4(uint32_t* r, uint32_t addr) {
    asm volatile("ldmatrix.sync.aligned.m8n8.x4.shared.b16 {%0,%1,%2,%3}, [%4];"
        : "=r"(r[0]), "=r"(r[1]), "=r"(r[2]), "=r"(r[3]) : "r"(addr));
}

__device__ __forceinline__ void mma_f16(float* c, const uint32_t* a,
                                        uint32_t b0, uint32_t b1) {
    asm volatile("mma.sync.aligned.m16n8k16.row.col.f32.f16.f16.f32 "
        "{%0,%1,%2,%3}, {%4,%5,%6,%7}, {%8,%9}, {%0,%1,%2,%3};"
        : "+f"(c[0]), "+f"(c[1]), "+f"(c[2]), "+f"(c[3])
        : "r"(a[0]), "r"(a[1]), "r"(a[2]), "r"(a[3]), "r"(b0), "r"(b1));
}

__device__ __forceinline__ float tanha(float x) {
    float y;
    asm("tanh.approx.f32 %0, %1;" : "=f"(y) : "f"(x));
    return y;
}
__device__ __forceinline__ float siga(float x) {
    return fmaf(tanha(0.5f * x), 0.5f, 0.5f);
}
__device__ __forceinline__ float2 tanh2(float a, float b) {
    __half2 hx = __floats2half2_rn(a, b);
    uint32_t xr = *(uint32_t*)&hx, yr;
    asm("tanh.approx.f16x2 %0, %1;" : "=r"(yr) : "r"(xr));
    return __half22float2(*(__half2*)&yr);
}
__device__ __forceinline__ float2 sig2(float a, float b) {
    float2 t = tanh2(0.5f * a, 0.5f * b);
    return make_float2(fmaf(t.x, 0.5f, 0.5f), fmaf(t.y, 0.5f, 0.5f));
}

#define CP_ASYNC16(dst_u32, src) \
    asm volatile("cp.async.ca.shared.global [%0], [%1], 16;" :: "r"(dst_u32), "l"(src) : "memory")
#define CP_COMMIT() asm volatile("cp.async.commit_group;" ::: "memory")
#define CP_WAIT0()  asm volatile("cp.async.wait_group 0;" ::: "memory")

// 8 fp32 -> 8 fp16, one 16B store into swizzled tile
__device__ __forceinline__ void cvt8_store_f16(const float* v, char* smem,
                                               int tile, uint32_t off) {
    uint32_t w[4];
    #pragma unroll
    for (int qq = 0; qq < 4; ++qq) {
        __half2 h = __floats2half2_rn(v[2 * qq], v[2 * qq + 1]);
        w[qq] = *(uint32_t*)&h;
    }
    *(uint4*)(smem + tile + off) = make_uint4(w[0], w[1], w[2], w[3]);
}

// x fp32 -> fp16 (one-time)
__global__ __launch_bounds__(256)
void x_convert_kernel(const float* __restrict__ x)
{
    size_t i8 = ((size_t)blockIdx.x * 256 + threadIdx.x) * 8;
    float4 v0 = *(const float4*)(x + i8);
    float4 v1 = *(const float4*)(x + i8 + 4);
    __half2 h0 = __floats2half2_rn(v0.x, v0.y);
    __half2 h1 = __floats2half2_rn(v0.z, v0.w);
    __half2 h2 = __floats2half2_rn(v1.x, v1.y);
    __half2 h3 = __floats2half2_rn(v1.z, v1.w);
    *(uint4*)(g_x16 + i8) = make_uint4(*(uint32_t*)&h0, *(uint32_t*)&h1,
                                       *(uint32_t*)&h2, *(uint32_t*)&h3);
}

__global__ __launch_bounds__(THREADS, 2)
void lstm_mma_kernel(const float* __restrict__ W_ih,
                     const float* __restrict__ W_hh,
                     const float* __restrict__ b_ih,
                     const float* __restrict__ b_hh,
                     const float* __restrict__ h0,
                     const float* __restrict__ c0)
{
    extern __shared__ char smem[];
    const uint32_t sbase = smem_u32(smem);
    float* sbias = (float*)(smem + SBIAS);

    const int tid  = threadIdx.x;
    const int warp = tid >> 5;
    const int lane = tid & 31;
    const int wm = warp & 1;            // M-warp (2)
    const int wn = warp >> 1;           // N-warp (4)
    const int mrow0 = wm * 32;
    const int nbase = wn * 64;          // permuted-B row base
    const int gid = lane >> 2;
    const int q   = lane & 3;
    const int jg  = wn * 16 + q * 4;    // this thread's hd base (4 contiguous)

    const int a_row_lane = ((lane >> 3) & 1) * 8 + (lane & 7);
    const int a_kadd     = (lane >> 4) * 8;
    const int b_row_lane = (lane >> 4) * 8 + (lane & 7);
    const int b_kadd     = ((lane >> 3) & 1) * 8;

    const int head  = blockIdx.y;
    const int node0 = blockIdx.x * NB;

    // per-thread staging chunk coords (2 chunks of 16B in the x-region)
    const int stg_n0 = tid >> 3;
    const int stg_k0 = (tid & 7) * 8;
    const int stg_n1 = (tid + THREADS) >> 3;
    const int stg_k1 = stg_k0;

    float c_reg[2][2][4];   // [mtile][rowhalf][joff]

    for (int l = 0; l < 2; ++l) {
        // ======== layer prologue ========
        const float* Wih_g = W_ih + (size_t)(l * N_HEADS + head) * (G_DIM * H_DIM);
        const float* Whh_g = W_hh + (size_t)(l * N_HEADS + head) * (G_DIM * H_DIM);

        // B tile, gate-interleave row permutation
        #pragma unroll 1
        for (int i = 0; i < 16; ++i) {
            int gidx = tid + i * THREADS;
            int row_out = gidx >> 4;
            int k8 = (gidx & 15) * 8;
            int tt = (row_out >> 3) & 7;
            int qq = (row_out >> 1) & 3;
            int bb = row_out & 1;
            int wnn = row_out >> 6;
            int g  = ((tt & 1) << 1) | bb;
            int jj = (wnn << 4) | (qq << 2) | (tt >> 1);
            const float* src = (k8 < 64) ? (Wih_g + (g * 64 + jj) * 64 + k8)
                                         : (Whh_g + (g * 64 + jj) * 64 + (k8 - 64));
            float v[8];
            float4 v0 = *(const float4*)(src);
            float4 v1 = *(const float4*)(src + 4);
            v[0]=v0.x; v[1]=v0.y; v[2]=v0.z; v[3]=v0.w;
            v[4]=v1.x; v[5]=v1.y; v[6]=v1.z; v[7]=v1.w;
            cvt8_store_f16(v, smem, SB, swzoff(32, row_out, k8));
        }
        // bias
        {
            const float* bi = b_ih + (size_t)(l * N_HEADS + head) * G_DIM;
            const float* bh = b_hh + (size_t)(l * N_HEADS + head) * G_DIM;
            sbias[tid] = bi[tid] + bh[tid];
        }
        // h0 -> A[0] h-region (k 64..127), fp32 -> fp16
        {
            const float* hsrc = h0 + ((size_t)(head * 2 + l) * N_NODES + node0) * H_DIM;
            #pragma unroll
            for (int i = 0; i < 2; ++i) {
                int gidx = tid + i * THREADS;
                int n  = gidx >> 3;
                int k8 = (gidx & 7) * 8;
                float v[8];
                float4 v0 = *(const float4*)(hsrc + n * 64 + k8);
                float4 v1 = *(const float4*)(hsrc + n * 64 + k8 + 4);
                v[0]=v0.x; v[1]=v0.y; v[2]=v0.z; v[3]=v0.w;
                v[4]=v1.x; v[5]=v1.y; v[6]=v1.z; v[7]=v1.w;
                cvt8_store_f16(v, smem, SA0, swzoff(8, n, 64 + k8));
            }
        }
        // c0 -> registers
        {
            const float* cbase = c0 + ((size_t)(head * 2 + l) * N_NODES + node0) * H_DIM;
            #pragma unroll
            for (int mt = 0; mt < 2; ++mt)
                #pragma unroll
                for (int rh = 0; rh < 2; ++rh) {
                    int rowL = mrow0 + mt * 16 + gid + rh * 8;
                    float4 v = *(const float4*)(cbase + (size_t)rowL * 64 + jg);
                    c_reg[mt][rh][0]=v.x; c_reg[mt][rh][1]=v.y;
                    c_reg[mt][rh][2]=v.z; c_reg[mt][rh][3]=v.w;
                }
        }
        // fp16 input stream for this layer
        const __half* in16 = (l == 0)
            ? (g_x16 + (size_t)node0 * H_DIM)
            : (g_hs0 + ((size_t)head * T_LEN * N_NODES + node0) * H_DIM);
        __half* out_base = ((l == 0) ? g_hs0 : g_hs1)
                         + (size_t)head * T_LEN * N_NODES * H_DIM;

        // x_0 -> A[0] x-region via cp.async
        CP_ASYNC16(sbase + SA0 + swzoff(8, stg_n0, stg_k0), in16 + stg_n0 * 64 + stg_k0);
        CP_ASYNC16(sbase + SA0 + swzoff(8, stg_n1, stg_k1), in16 + stg_n1 * 64 + stg_k1);
        CP_COMMIT(); CP_WAIT0();
        __syncthreads();

        // hoist Whh B-fragments (kc = 6..7) into registers for the whole scan
        uint32_t bfr[2][4][4];
        #pragma unroll
        for (int kh = 0; kh < 2; ++kh)
            #pragma unroll
            for (int nt2 = 0; nt2 < 4; ++nt2) {
                uint32_t off = swzoff(32, nbase + nt2 * 16 + b_row_lane,
                                      (6 + kh) * 16 + b_kadd);
                ldsm4(bfr[kh][nt2], sbase + SB + off);
            }

        // ======== scan (double-buffered A, ONE sync per step) ========
        for (int t = 0; t < T_LEN; ++t) {
            const int SAc = (t & 1) ? SA1 : SA0;
            const int SAn = (t & 1) ? SA0 : SA1;
            const bool notlast = (t + 1 < T_LEN);

            // stage x_{t+1} into A[nxt] x-region via cp.async (overlaps MMA)
            if (notlast) {
                const __half* srcn = in16 + (size_t)(t + 1) * N_NODES * H_DIM;
                CP_ASYNC16(sbase + SAn + swzoff(8, stg_n0, stg_k0), srcn + stg_n0 * 64 + stg_k0);
                CP_ASYNC16(sbase + SAn + swzoff(8, stg_n1, stg_k1), srcn + stg_n1 * 64 + stg_k1);
                CP_COMMIT();
            }

            // accum, bias-initialized
            float acc[2][8][4];
            #pragma unroll
            for (int nt = 0; nt < 8; ++nt) {
                float bv0 = sbias[(((nt & 1) << 1) | 0) * 64 + jg + (nt >> 1)];
                float bv1 = sbias[(((nt & 1) << 1) | 1) * 64 + jg + (nt >> 1)];
                #pragma unroll
                for (int mt = 0; mt < 2; ++mt) {
                    acc[mt][nt][0] = bv0; acc[mt][nt][1] = bv1;
                    acc[mt][nt][2] = bv0; acc[mt][nt][3] = bv1;
                }
            }

            // MMA part 1: kc 0..5 with B from SMEM
            #pragma unroll
            for (int kc = 0; kc < 6; ++kc) {
                int k0 = kc * 16;
                uint32_t af[2][4];
                #pragma unroll
                for (int mt = 0; mt < 2; ++mt) {
                    uint32_t off = swzoff(8, mrow0 + mt * 16 + a_row_lane, k0 + a_kadd);
                    ldsm4(af[mt], sbase + SAc + off);
                }
                #pragma unroll
                for (int nt2 = 0; nt2 < 4; ++nt2) {
                    uint32_t off = swzoff(32, nbase + nt2 * 16 + b_row_lane, k0 + b_kadd);
                    uint32_t bh[4];
                    ldsm4(bh, sbase + SB + off);
                    #pragma unroll
                    for (int hf = 0; hf < 2; ++hf)
                        #pragma unroll
                        for (int mt = 0; mt < 2; ++mt)
                            mma_f16(acc[mt][nt2 * 2 + hf], af[mt], bh[hf*2], bh[hf*2+1]);
                }
            }
            // MMA part 2: kc 6..7 with hoisted B fragments
            #pragma unroll
            for (int kh = 0; kh < 2; ++kh) {
                int k0 = (6 + kh) * 16;
                uint32_t af[2][4];
                #pragma unroll
                for (int mt = 0; mt < 2; ++mt) {
                    uint32_t off = swzoff(8, mrow0 + mt * 16 + a_row_lane, k0 + a_kadd);
                    ldsm4(af[mt], sbase + SAc + off);
                }
                #pragma unroll
                for (int nt2 = 0; nt2 < 4; ++nt2)
                    #pragma unroll
                    for (int hf = 0; hf < 2; ++hf)
                        #pragma unroll
                        for (int mt = 0; mt < 2; ++mt)
                            mma_f16(acc[mt][nt2 * 2 + hf], af[mt],
                                    bfr[kh][nt2][hf*2], bfr[kh][nt2][hf*2+1]);
            }

            // epilogue: cell update; h -> GMEM (+ A[nxt] h-region unless last step)
            #pragma unroll
            for (int mt = 0; mt < 2; ++mt)
                #pragma unroll
                for (int rh = 0; rh < 2; ++rh) {
                    int rowL = mrow0 + mt * 16 + gid + rh * 8;
                    float iv[4], fv[4], gv[4], ov[4];
                    #pragma unroll
                    for (int jo = 0; jo < 4; ++jo) {
                        iv[jo] = acc[mt][2*jo  ][rh*2 + 0];
                        fv[jo] = acc[mt][2*jo  ][rh*2 + 1];
                        gv[jo] = acc[mt][2*jo+1][rh*2 + 0];
                        ov[jo] = acc[mt][2*jo+1][rh*2 + 1];
                    }
                    float2 tg01 = tanh2(gv[0], gv[1]);
                    float2 tg23 = tanh2(gv[2], gv[3]);
                    float tg[4] = {tg01.x, tg01.y, tg23.x, tg23.y};
                    float2 si01 = sig2(iv[0], iv[1]);
                    float2 si23 = sig2(iv[2], iv[3]);
                    float si[4] = {si01.x, si01.y, si23.x, si23.y};
                    float cc[4];
                    #pragma unroll
                    for (int jo = 0; jo < 4; ++jo) {
                        cc[jo] = siga(fv[jo]) * c_reg[mt][rh][jo] + si[jo] * tg[jo];
                        c_reg[mt][rh][jo] = cc[jo];
                    }
                    float2 tc01 = tanh2(cc[0], cc[1]);
                    float2 tc23 = tanh2(cc[2], cc[3]);
                    float tc[4] = {tc01.x, tc01.y, tc23.x, tc23.y};
                    float2 so01 = sig2(ov[0], ov[1]);
                    float2 so23 = sig2(ov[2], ov[3]);
                    float so[4] = {so01.x, so01.y, so23.x, so23.y};
                    float hv[4];
                    #pragma unroll
                    for (int jo = 0; jo < 4; ++jo)
                        hv[jo] = so[jo] * tc[jo];

                    __half2 h0p = __floats2half2_rn(hv[0], hv[1]);
                    __half2 h1p = __floats2half2_rn(hv[2], hv[3]);
                    uint2 hp = make_uint2(*(uint32_t*)&h0p, *(uint32_t*)&h1p);
                    *(uint2*)(out_base + ((size_t)t * N_NODES + node0 + rowL) * H_DIM + jg) = hp;
                    if (notlast)
                        *(uint2*)(smem + SAn + swzoff(8, rowL, 64 + jg)) = hp;
                }
            if (notlast) { CP_WAIT0(); }
            __syncthreads();
        }
        __threadfence();   // layer-0 h STGs visible before layer-1 cp.async reads
        __syncthreads();
    }
}

// out[o][n][hd] = sum_c hs1[c][n][hd] * conv_w[o][c] + conv_b[o]
// 8 elems/thread: 1 LDG.128 + 12 LDS + 96 FFMA per channel
__global__ __launch_bounds__(256, 2)
void conv_kernel(const float* __restrict__ conv_w,
                 const float* __restrict__ conv_b,
                 float* __restrict__ out)
{
    __shared__ float sw[T_LEN * N_HEADS * T_LEN];
    __shared__ float sb[T_LEN];
    for (int i = threadIdx.x; i < T_LEN * N_HEADS * T_LEN; i += 256)
        sw[i] = conv_w[i];
    if (threadIdx.x < T_LEN) sb[threadIdx.x] = conv_b[threadIdx.x];
    __syncthreads();

    const size_t stride = (size_t)N_NODES * H_DIM;
    size_t nh8 = ((size_t)blockIdx.x * 256 + threadIdx.x) * 8;

    float acc[T_LEN][8];
    #pragma unroll
    for (int o = 0; o < T_LEN; ++o) {
        float b = sb[o];
        #pragma unroll
        for (int e = 0; e < 8; ++e) acc[o][e] = b;
    }
    #pragma unroll 4
    for (int c = 0; c < N_HEADS * T_LEN; ++c) {
        uint4 raw = *(const uint4*)(g_hs1 + (size_t)c * stride + nh8);
        float2 f0 = __half22float2(*(__half2*)&raw.x);
        float2 f1 = __half22float2(*(__half2*)&raw.y);
        float2 f2 = __half22float2(*(__half2*)&raw.z);
        float2 f3 = __half22float2(*(__half2*)&raw.w);
        float fx[8] = {f0.x, f0.y, f1.x, f1.y, f2.x, f2.y, f3.x, f3.y};
        #pragma unroll
        for (int o = 0; o < T_LEN; ++o) {
            float w = sw[o * (N_HEADS * T_LEN) + c];
            #pragma unroll
            for (int e = 0; e < 8; ++e)
                acc[o][e] = fmaf(fx[e], w, acc[o][e]);
        }
    }
    #pragma unroll
    for (int o = 0; o < T_LEN; ++o) {
        *(float4*)(out + (size_t)o * stride + nh8) =
            make_float4(acc[o][0], acc[o][1], acc[o][2], acc[o][3]);
        *(float4*)(out + (size_t)o * stride + nh8 + 4) =
            make_float4(acc[o][4], acc[o][5], acc[o][6], acc[o][7]);
    }
}

extern "C" void kernel_launch(void* const* d_in, const int* in_sizes, int n_in,
                              void* d_out, int out_size)
{
    const float* x      = (const float*)d_in[0];
    const float* W_ih   = (const float*)d_in[1];
    const float* W_hh   = (const float*)d_in[2];
    const float* b_ih   = (const float*)d_in[3];
    const float* b_hh   = (const float*)d_in[4];
    const float* h0     = (const float*)d_in[5];
    const float* c0     = (const float*)d_in[6];
    const float* conv_w = (const float*)d_in[7];
    const float* conv_b = (const float*)d_in[8];
    float* out = (float*)d_out;

    cudaFuncSetAttribute(lstm_mma_kernel,
                         cudaFuncAttributeMaxDynamicSharedMemorySize, SMEM_TOTAL);

    // x fp32 -> fp16
    x_convert_kernel<<<(T_LEN * N_NODES * H_DIM) / (8 * 256), 256>>>(x);

    dim3 grid(N_NODES / NB, N_HEADS);     // 256 x 8 = 2048 CTAs
    lstm_mma_kernel<<<grid, THREADS, SMEM_TOTAL>>>(W_ih, W_hh, b_ih, b_hh, h0, c0);

    conv_kernel<<<(N_NODES * H_DIM) / (8 * 256), 256>>>(conv_w, conv_b, out);
}

// round 15
// speedup vs baseline: 2.2388x; 1.0027x over previous
#include <cuda_runtime.h>
#include <cuda_fp16.h>
#include <cstdint>

#define T_LEN   12
#define N_HEADS 8
#define N_NODES 16384
#define H_DIM   64
#define G_DIM   256
#define NB      64           // nodes per CTA (= GEMM M)
#define THREADS 256

// ---- LSTM shared memory layout (bytes) ----
#define SA0     0            // A tile buf0: [64 rows][128 k] fp16 swizzled (16384)
#define SA1     16384        // A tile buf1                                  (16384)
#define SB      32768        // B tile: [256 rows][128 k] fp16              (65536)
#define SBIAS   98304        // bias fp32 [256]                             (1024)
#define SMEM_TOTAL 99328

// Scratch
__device__ __half g_x16[(size_t)T_LEN * N_NODES * H_DIM];            // x in fp16
__device__ __half g_hs0[(size_t)N_HEADS * T_LEN * N_NODES * H_DIM];  // layer-0 h
__device__ __half g_hs1[(size_t)N_HEADS * T_LEN * N_NODES * H_DIM];  // layer-1 h

__device__ __forceinline__ uint32_t swzoff(int R8, int row, int k) {
    uint32_t off = (uint32_t)((((row >> 3) + (k >> 6) * R8) << 10)
                 + ((row & 7) << 7) + ((k & 63) << 1));
    return off ^ ((off >> 3) & 0x70);
}

__device__ __forceinline__ uint32_t smem_u32(const void* p) {
    uint32_t a;
    asm("{ .reg .u64 t; cvta.to.shared.u64 t, %1; cvt.u32.u64 %0, t; }" : "=r"(a) : "l"(p));
    return a;
}

__device__ __forceinline__ void ldsm4(uint32_t* r, uint32_t addr) {
    asm volatile("ldmatrix.sync.aligned.m8n8.x4.shared.b16 {%0,%1,%2,%3}, [%4];"
        : "=r"(r[0]), "=r"(r[1]), "=r"(r[2]), "=r"(r[3]) : "r"(addr));
}

__device__ __forceinline__ void mma_f16(float* c, const uint32_t* a,
                                        uint32_t b0, uint32_t b1) {
    asm volatile("mma.sync.aligned.m16n8k16.row.col.f32.f16.f16.f32 "
        "{%0,%1,%2,%3}, {%4,%5,%6,%7}, {%8,%9}, {%0,%1,%2,%3};"
        : "+f"(c[0]), "+f"(c[1]), "+f"(c[2]), "+f"(c[3])
        : "r"(a[0]), "r"(a[1]), "r"(a[2]), "r"(a[3]), "r"(b0), "r"(b1));
}

__device__ __forceinline__ float tanha(float x) {
    float y;
    asm("tanh.approx.f32 %0, %1;" : "=f"(y) : "f"(x));
    return y;
}
__device__ __forceinline__ float siga(float x) {
    return fmaf(tanha(0.5f * x), 0.5f, 0.5f);
}
__device__ __forceinline__ float2 tanh2(float a, float b) {
    __half2 hx = __floats2half2_rn(a, b);
    uint32_t xr = *(uint32_t*)&hx, yr;
    asm("tanh.approx.f16x2 %0, %1;" : "=r"(yr) : "r"(xr));
    return __half22float2(*(__half2*)&yr);
}
__device__ __forceinline__ float2 sig2(float a, float b) {
    float2 t = tanh2(0.5f * a, 0.5f * b);
    return make_float2(fmaf(t.x, 0.5f, 0.5f), fmaf(t.y, 0.5f, 0.5f));
}

#define CP_ASYNC16(dst_u32, src) \
    asm volatile("cp.async.ca.shared.global [%0], [%1], 16;" :: "r"(dst_u32), "l"(src) : "memory")
#define CP_COMMIT() asm volatile("cp.async.commit_group;" ::: "memory")
#define CP_WAIT0()  asm volatile("cp.async.wait_group 0;" ::: "memory")

// 8 fp32 -> 8 fp16, one 16B store into swizzled tile
__device__ __forceinline__ void cvt8_store_f16(const float* v, char* smem,
                                               int tile, uint32_t off) {
    uint32_t w[4];
    #pragma unroll
    for (int qq = 0; qq < 4; ++qq) {
        __half2 h = __floats2half2_rn(v[2 * qq], v[2 * qq + 1]);
        w[qq] = *(uint32_t*)&h;
    }
    *(uint4*)(smem + tile + off) = make_uint4(w[0], w[1], w[2], w[3]);
}

// x fp32 -> fp16 (one-time)
__global__ __launch_bounds__(256)
void x_convert_kernel(const float* __restrict__ x)
{
    size_t i8 = ((size_t)blockIdx.x * 256 + threadIdx.x) * 8;
    float4 v0 = *(const float4*)(x + i8);
    float4 v1 = *(const float4*)(x + i8 + 4);
    __half2 h0 = __floats2half2_rn(v0.x, v0.y);
    __half2 h1 = __floats2half2_rn(v0.z, v0.w);
    __half2 h2 = __floats2half2_rn(v1.x, v1.y);
    __half2 h3 = __floats2half2_rn(v1.z, v1.w);
    *(uint4*)(g_x16 + i8) = make_uint4(*(uint32_t*)&h0, *(uint32_t*)&h1,
                                       *(uint32_t*)&h2, *(uint32_t*)&h3);
}

__global__ __launch_bounds__(THREADS, 2)
void lstm_mma_kernel(const float* __restrict__ W_ih,
                     const float* __restrict__ W_hh,
                     const float* __restrict__ b_ih,
                     const float* __restrict__ b_hh,
                     const float* __restrict__ h0,
                     const float* __restrict__ c0)
{
    extern __shared__ char smem[];
    const uint32_t sbase = smem_u32(smem);
    float* sbias = (float*)(smem + SBIAS);

    const int tid  = threadIdx.x;
    const int warp = tid >> 5;
    const int lane = tid & 31;
    const int wm = warp & 1;            // M-warp (2)
    const int wn = warp >> 1;           // N-warp (4)
    const int mrow0 = wm * 32;
    const int nbase = wn * 64;          // permuted-B row base
    const int gid = lane >> 2;
    const int q   = lane & 3;
    const int jg  = wn * 16 + q * 4;    // this thread's hd base (4 contiguous)

    const int a_row_lane = ((lane >> 3) & 1) * 8 + (lane & 7);
    const int a_kadd     = (lane >> 4) * 8;
    const int b_row_lane = (lane >> 4) * 8 + (lane & 7);
    const int b_kadd     = ((lane >> 3) & 1) * 8;

    const int head  = blockIdx.y;
    const int node0 = blockIdx.x * NB;

    // per-thread staging chunk coords (2 chunks of 16B in the x-region)
    const int stg_n0 = tid >> 3;
    const int stg_k0 = (tid & 7) * 8;
    const int stg_n1 = (tid + THREADS) >> 3;
    const int stg_k1 = stg_k0;

    float c_reg[2][2][4];   // [mtile][rowhalf][joff]

    for (int l = 0; l < 2; ++l) {
        // ======== layer prologue ========
        const float* Wih_g = W_ih + (size_t)(l * N_HEADS + head) * (G_DIM * H_DIM);
        const float* Whh_g = W_hh + (size_t)(l * N_HEADS + head) * (G_DIM * H_DIM);

        // B tile, gate-interleave row permutation
        #pragma unroll 1
        for (int i = 0; i < 16; ++i) {
            int gidx = tid + i * THREADS;
            int row_out = gidx >> 4;
            int k8 = (gidx & 15) * 8;
            int tt = (row_out >> 3) & 7;
            int qq = (row_out >> 1) & 3;
            int bb = row_out & 1;
            int wnn = row_out >> 6;
            int g  = ((tt & 1) << 1) | bb;
            int jj = (wnn << 4) | (qq << 2) | (tt >> 1);
            const float* src = (k8 < 64) ? (Wih_g + (g * 64 + jj) * 64 + k8)
                                         : (Whh_g + (g * 64 + jj) * 64 + (k8 - 64));
            float v[8];
            float4 v0 = *(const float4*)(src);
            float4 v1 = *(const float4*)(src + 4);
            v[0]=v0.x; v[1]=v0.y; v[2]=v0.z; v[3]=v0.w;
            v[4]=v1.x; v[5]=v1.y; v[6]=v1.z; v[7]=v1.w;
            cvt8_store_f16(v, smem, SB, swzoff(32, row_out, k8));
        }
        // bias
        {
            const float* bi = b_ih + (size_t)(l * N_HEADS + head) * G_DIM;
            const float* bh = b_hh + (size_t)(l * N_HEADS + head) * G_DIM;
            sbias[tid] = bi[tid] + bh[tid];
        }
        // h0 -> A[0] h-region (k 64..127), fp32 -> fp16
        {
            const float* hsrc = h0 + ((size_t)(head * 2 + l) * N_NODES + node0) * H_DIM;
            #pragma unroll
            for (int i = 0; i < 2; ++i) {
                int gidx = tid + i * THREADS;
                int n  = gidx >> 3;
                int k8 = (gidx & 7) * 8;
                float v[8];
                float4 v0 = *(const float4*)(hsrc + n * 64 + k8);
                float4 v1 = *(const float4*)(hsrc + n * 64 + k8 + 4);
                v[0]=v0.x; v[1]=v0.y; v[2]=v0.z; v[3]=v0.w;
                v[4]=v1.x; v[5]=v1.y; v[6]=v1.z; v[7]=v1.w;
                cvt8_store_f16(v, smem, SA0, swzoff(8, n, 64 + k8));
            }
        }
        // c0 -> registers
        {
            const float* cbase = c0 + ((size_t)(head * 2 + l) * N_NODES + node0) * H_DIM;
            #pragma unroll
            for (int mt = 0; mt < 2; ++mt)
                #pragma unroll
                for (int rh = 0; rh < 2; ++rh) {
                    int rowL = mrow0 + mt * 16 + gid + rh * 8;
                    float4 v = *(const float4*)(cbase + (size_t)rowL * 64 + jg);
                    c_reg[mt][rh][0]=v.x; c_reg[mt][rh][1]=v.y;
                    c_reg[mt][rh][2]=v.z; c_reg[mt][rh][3]=v.w;
                }
        }
        // fp16 input stream for this layer
        const __half* in16 = (l == 0)
            ? (g_x16 + (size_t)node0 * H_DIM)
            : (g_hs0 + ((size_t)head * T_LEN * N_NODES + node0) * H_DIM);
        __half* out_base = ((l == 0) ? g_hs0 : g_hs1)
                         + (size_t)head * T_LEN * N_NODES * H_DIM;

        // x_0 -> A[0] x-region via cp.async
        CP_ASYNC16(sbase + SA0 + swzoff(8, stg_n0, stg_k0), in16 + stg_n0 * 64 + stg_k0);
        CP_ASYNC16(sbase + SA0 + swzoff(8, stg_n1, stg_k1), in16 + stg_n1 * 64 + stg_k1);
        CP_COMMIT(); CP_WAIT0();
        __syncthreads();

        // hoist Whh B-fragments (kc = 6..7) into registers for the whole scan
        uint32_t bfr[2][4][4];
        #pragma unroll
        for (int kh = 0; kh < 2; ++kh)
            #pragma unroll
            for (int nt2 = 0; nt2 < 4; ++nt2) {
                uint32_t off = swzoff(32, nbase + nt2 * 16 + b_row_lane,
                                      (6 + kh) * 16 + b_kadd);
                ldsm4(bfr[kh][nt2], sbase + SB + off);
            }

        // ======== scan (double-buffered A, ONE sync per step) ========
        for (int t = 0; t < T_LEN; ++t) {
            const int SAc = (t & 1) ? SA1 : SA0;
            const int SAn = (t & 1) ? SA0 : SA1;
            const bool notlast = (t + 1 < T_LEN);

            // stage x_{t+1} into A[nxt] x-region via cp.async (overlaps MMA)
            if (notlast) {
                const __half* srcn = in16 + (size_t)(t + 1) * N_NODES * H_DIM;
                CP_ASYNC16(sbase + SAn + swzoff(8, stg_n0, stg_k0), srcn + stg_n0 * 64 + stg_k0);
                CP_ASYNC16(sbase + SAn + swzoff(8, stg_n1, stg_k1), srcn + stg_n1 * 64 + stg_k1);
                CP_COMMIT();
            }

            // accum, bias-initialized
            float acc[2][8][4];
            #pragma unroll
            for (int nt = 0; nt < 8; ++nt) {
                float bv0 = sbias[(((nt & 1) << 1) | 0) * 64 + jg + (nt >> 1)];
                float bv1 = sbias[(((nt & 1) << 1) | 1) * 64 + jg + (nt >> 1)];
                #pragma unroll
                for (int mt = 0; mt < 2; ++mt) {
                    acc[mt][nt][0] = bv0; acc[mt][nt][1] = bv1;
                    acc[mt][nt][2] = bv0; acc[mt][nt][3] = bv1;
                }
            }

            // MMA part 1: kc 0..5 with B from SMEM
            #pragma unroll
            for (int kc = 0; kc < 6; ++kc) {
                int k0 = kc * 16;
                uint32_t af[2][4];
                #pragma unroll
                for (int mt = 0; mt < 2; ++mt) {
                    uint32_t off = swzoff(8, mrow0 + mt * 16 + a_row_lane, k0 + a_kadd);
                    ldsm4(af[mt], sbase + SAc + off);
                }
                #pragma unroll
                for (int nt2 = 0; nt2 < 4; ++nt2) {
                    uint32_t off = swzoff(32, nbase + nt2 * 16 + b_row_lane, k0 + b_kadd);
                    uint32_t bh[4];
                    ldsm4(bh, sbase + SB + off);
                    #pragma unroll
                    for (int hf = 0; hf < 2; ++hf)
                        #pragma unroll
                        for (int mt = 0; mt < 2; ++mt)
                            mma_f16(acc[mt][nt2 * 2 + hf], af[mt], bh[hf*2], bh[hf*2+1]);
                }
            }
            // MMA part 2: kc 6..7 with hoisted B fragments
            #pragma unroll
            for (int kh = 0; kh < 2; ++kh) {
                int k0 = (6 + kh) * 16;
                uint32_t af[2][4];
                #pragma unroll
                for (int mt = 0; mt < 2; ++mt) {
                    uint32_t off = swzoff(8, mrow0 + mt * 16 + a_row_lane, k0 + a_kadd);
                    ldsm4(af[mt], sbase + SAc + off);
                }
                #pragma unroll
                for (int nt2 = 0; nt2 < 4; ++nt2)
                    #pragma unroll
                    for (int hf = 0; hf < 2; ++hf)
                        #pragma unroll
                        for (int mt = 0; mt < 2; ++mt)
                            mma_f16(acc[mt][nt2 * 2 + hf], af[mt],
                                    bfr[kh][nt2][hf*2], bfr[kh][nt2][hf*2+1]);
            }

            // epilogue: cell update; h -> GMEM (+ A[nxt] h-region unless last step)
            #pragma unroll
            for (int mt = 0; mt < 2; ++mt)
                #pragma unroll
                for (int rh = 0; rh < 2; ++rh) {
                    int rowL = mrow0 + mt * 16 + gid + rh * 8;
                    float iv[4], fv[4], gv[4], ov[4];
                    #pragma unroll
                    for (int jo = 0; jo < 4; ++jo) {
                        iv[jo] = acc[mt][2*jo  ][rh*2 + 0];
                        fv[jo] = acc[mt][2*jo  ][rh*2 + 1];
                        gv[jo] = acc[mt][2*jo+1][rh*2 + 0];
                        ov[jo] = acc[mt][2*jo+1][rh*2 + 1];
                    }
                    float2 tg01 = tanh2(gv[0], gv[1]);
                    float2 tg23 = tanh2(gv[2], gv[3]);
                    float tg[4] = {tg01.x, tg01.y, tg23.x, tg23.y};
                    float2 si01 = sig2(iv[0], iv[1]);
                    float2 si23 = sig2(iv[2], iv[3]);
                    float si[4] = {si01.x, si01.y, si23.x, si23.y};
                    float cc[4];
                    #pragma unroll
                    for (int jo = 0; jo < 4; ++jo) {
                        cc[jo] = siga(fv[jo]) * c_reg[mt][rh][jo] + si[jo] * tg[jo];
                        c_reg[mt][rh][jo] = cc[jo];
                    }
                    float2 tc01 = tanh2(cc[0], cc[1]);
                    float2 tc23 = tanh2(cc[2], cc[3]);
                    float tc[4] = {tc01.x, tc01.y, tc23.x, tc23.y};
                    float2 so01 = sig2(ov[0], ov[1]);
                    float2 so23 = sig2(ov[2], ov[3]);
                    float so[4] = {so01.x, so01.y, so23.x, so23.y};
                    float hv[4];
                    #pragma unroll
                    for (int jo = 0; jo < 4; ++jo)
                        hv[jo] = so[jo] * tc[jo];

                    __half2 h0p = __floats2half2_rn(hv[0], hv[1]);
                    __half2 h1p = __floats2half2_rn(hv[2], hv[3]);
                    uint2 hp = make_uint2(*(uint32_t*)&h0p, *(uint32_t*)&h1p);
                    *(uint2*)(out_base + ((size_t)t * N_NODES + node0 + rowL) * H_DIM + jg) = hp;
                    if (notlast)
                        *(uint2*)(smem + SAn + swzoff(8, rowL, 64 + jg)) = hp;
                }
            if (notlast) { CP_WAIT0(); }
            __syncthreads();
        }
        __threadfence();   // layer-0 h STGs visible before layer-1 cp.async reads
        __syncthreads();
    }
}

// out[o][n][hd] = sum_c hs1[c][n][hd] * conv_w[o][c] + conv_b[o]
// R10 4-elem form; occupancy raised to 3 CTAs/SM (85-reg cap)
__global__ __launch_bounds__(256, 3)
void conv_kernel(const float* __restrict__ conv_w,
                 const float* __restrict__ conv_b,
                 float* __restrict__ out)
{
    __shared__ float sw[T_LEN * N_HEADS * T_LEN];
    __shared__ float sb[T_LEN];
    for (int i = threadIdx.x; i < T_LEN * N_HEADS * T_LEN; i += 256)
        sw[i] = conv_w[i];
    if (threadIdx.x < T_LEN) sb[threadIdx.x] = conv_b[threadIdx.x];
    __syncthreads();

    const size_t stride = (size_t)N_NODES * H_DIM;
    size_t nh4 = ((size_t)blockIdx.x * 256 + threadIdx.x) * 4;

    float acc[T_LEN][4];
    #pragma unroll
    for (int o = 0; o < T_LEN; ++o) {
        float b = sb[o];
        acc[o][0] = b; acc[o][1] = b; acc[o][2] = b; acc[o][3] = b;
    }
    #pragma unroll 4
    for (int c = 0; c < N_HEADS * T_LEN; ++c) {
        uint2 raw = *(const uint2*)(g_hs1 + (size_t)c * stride + nh4);
        float2 f0 = __half22float2(*(__half2*)&raw.x);
        float2 f1 = __half22float2(*(__half2*)&raw.y);
        #pragma unroll
        for (int o = 0; o < T_LEN; ++o) {
            float w = sw[o * (N_HEADS * T_LEN) + c];
            acc[o][0] += f0.x * w; acc[o][1] += f0.y * w;
            acc[o][2] += f1.x * w; acc[o][3] += f1.y * w;
        }
    }
    #pragma unroll
    for (int o = 0; o < T_LEN; ++o)
        *(float4*)(out + (size_t)o * stride + nh4) =
            make_float4(acc[o][0], acc[o][1], acc[o][2], acc[o][3]);
}

extern "C" void kernel_launch(void* const* d_in, const int* in_sizes, int n_in,
                              void* d_out, int out_size)
{
    const float* x      = (const float*)d_in[0];
    const float* W_ih   = (const float*)d_in[1];
    const float* W_hh   = (const float*)d_in[2];
    const float* b_ih   = (const float*)d_in[3];
    const float* b_hh   = (const float*)d_in[4];
    const float* h0     = (const float*)d_in[5];
    const float* c0     = (const float*)d_in[6];
    const float* conv_w = (const float*)d_in[7];
    const float* conv_b = (const float*)d_in[8];
    float* out = (float*)d_out;

    cudaFuncSetAttribute(lstm_mma_kernel,
                         cudaFuncAttributeMaxDynamicSharedMemorySize, SMEM_TOTAL);

    // x fp32 -> fp16
    x_convert_kernel<<<(T_LEN * N_NODES * H_DIM) / (8 * 256), 256>>>(x);

    dim3 grid(N_NODES / NB, N_HEADS);     // 256 x 8 = 2048 CTAs
    lstm_mma_kernel<<<grid, THREADS, SMEM_TOTAL>>>(W_ih, W_hh, b_ih, b_hh, h0, c0);

    conv_kernel<<<(N_NODES * H_DIM) / (4 * 256), 256>>>(conv_w, conv_b, out);
}

// round 16
// speedup vs baseline: 2.4142x; 1.0783x over previous
#include <cuda_runtime.h>
#include <cuda_fp16.h>
#include <cstdint>

#define T_LEN   12
#define N_HEADS 8
#define N_NODES 16384
#define H_DIM   64
#define G_DIM   256
#define NB      64           // nodes per CTA (= GEMM M)
#define THREADS 256

// ---- LSTM shared memory layout (bytes) ----
#define SA0     0            // A tile buf0: [64 rows][128 k] fp16 swizzled (16384)
#define SA1     16384        // A tile buf1                                  (16384)
#define SB      32768        // B tile: [256 rows][128 k] fp16              (65536)
#define SBIAS   98304        // bias fp32 [256]                             (1024)
#define SMEM_TOTAL 99328

// Scratch
__device__ __half g_x16[(size_t)T_LEN * N_NODES * H_DIM];            // x in fp16
__device__ __half g_hs0[(size_t)N_HEADS * T_LEN * N_NODES * H_DIM];  // layer-0 h
__device__ __half g_hs1[(size_t)N_HEADS * T_LEN * N_NODES * H_DIM];  // layer-1 h

__device__ __forceinline__ uint32_t swzoff(int R8, int row, int k) {
    uint32_t off = (uint32_t)((((row >> 3) + (k >> 6) * R8) << 10)
                 + ((row & 7) << 7) + ((k & 63) << 1));
    return off ^ ((off >> 3) & 0x70);
}

__device__ __forceinline__ uint32_t smem_u32(const void* p) {
    uint32_t a;
    asm("{ .reg .u64 t; cvta.to.shared.u64 t, %1; cvt.u32.u64 %0, t; }" : "=r"(a) : "l"(p));
    return a;
}

__device__ __forceinline__ void ldsm4(uint32_t* r, uint32_t addr) {
    asm volatile("ldmatrix.sync.aligned.m8n8.x4.shared.b16 {%0,%1,%2,%3}, [%4];"
        : "=r"(r[0]), "=r"(r[1]), "=r"(r[2]), "=r"(r[3]) : "r"(addr));
}

__device__ __forceinline__ void mma_f16(float* c, const uint32_t* a,
                                        uint32_t b0, uint32_t b1) {
    asm volatile("mma.sync.aligned.m16n8k16.row.col.f32.f16.f16.f32 "
        "{%0,%1,%2,%3}, {%4,%5,%6,%7}, {%8,%9}, {%0,%1,%2,%3};"
        : "+f"(c[0]), "+f"(c[1]), "+f"(c[2]), "+f"(c[3])
        : "r"(a[0]), "r"(a[1]), "r"(a[2]), "r"(a[3]), "r"(b0), "r"(b1));
}

__device__ __forceinline__ float tanha(float x) {
    float y;
    asm("tanh.approx.f32 %0, %1;" : "=f"(y) : "f"(x));
    return y;
}
__device__ __forceinline__ float siga(float x) {
    return fmaf(tanha(0.5f * x), 0.5f, 0.5f);
}
__device__ __forceinline__ float2 tanh2(float a, float b) {
    __half2 hx = __floats2half2_rn(a, b);
    uint32_t xr = *(uint32_t*)&hx, yr;
    asm("tanh.approx.f16x2 %0, %1;" : "=r"(yr) : "r"(xr));
    return __half22float2(*(__half2*)&yr);
}
__device__ __forceinline__ float2 sig2(float a, float b) {
    float2 t = tanh2(0.5f * a, 0.5f * b);
    return make_float2(fmaf(t.x, 0.5f, 0.5f), fmaf(t.y, 0.5f, 0.5f));
}

#define CP_ASYNC16(dst_u32, src) \
    asm volatile("cp.async.ca.shared.global [%0], [%1], 16;" :: "r"(dst_u32), "l"(src) : "memory")
#define CP_COMMIT() asm volatile("cp.async.commit_group;" ::: "memory")
#define CP_WAIT0()  asm volatile("cp.async.wait_group 0;" ::: "memory")

// 8 fp32 -> 8 fp16, one 16B store into swizzled tile
__device__ __forceinline__ void cvt8_store_f16(const float* v, char* smem,
                                               int tile, uint32_t off) {
    uint32_t w[4];
    #pragma unroll
    for (int qq = 0; qq < 4; ++qq) {
        __half2 h = __floats2half2_rn(v[2 * qq], v[2 * qq + 1]);
        w[qq] = *(uint32_t*)&h;
    }
    *(uint4*)(smem + tile + off) = make_uint4(w[0], w[1], w[2], w[3]);
}

// x fp32 -> fp16 (one-time)
__global__ __launch_bounds__(256)
void x_convert_kernel(const float* __restrict__ x)
{
    size_t i8 = ((size_t)blockIdx.x * 256 + threadIdx.x) * 8;
    float4 v0 = *(const float4*)(x + i8);
    float4 v1 = *(const float4*)(x + i8 + 4);
    __half2 h0 = __floats2half2_rn(v0.x, v0.y);
    __half2 h1 = __floats2half2_rn(v0.z, v0.w);
    __half2 h2 = __floats2half2_rn(v1.x, v1.y);
    __half2 h3 = __floats2half2_rn(v1.z, v1.w);
    *(uint4*)(g_x16 + i8) = make_uint4(*(uint32_t*)&h0, *(uint32_t*)&h1,
                                       *(uint32_t*)&h2, *(uint32_t*)&h3);
}

__global__ __launch_bounds__(THREADS, 2)
void lstm_mma_kernel(const float* __restrict__ W_ih,
                     const float* __restrict__ W_hh,
                     const float* __restrict__ b_ih,
                     const float* __restrict__ b_hh,
                     const float* __restrict__ h0,
                     const float* __restrict__ c0)
{
    extern __shared__ char smem[];
    const uint32_t sbase = smem_u32(smem);
    float* sbias = (float*)(smem + SBIAS);

    const int tid  = threadIdx.x;
    const int warp = tid >> 5;
    const int lane = tid & 31;
    const int wm = warp & 1;            // M-warp (2)
    const int wn = warp >> 1;           // N-warp (4)
    const int mrow0 = wm * 32;
    const int nbase = wn * 64;          // permuted-B row base
    const int gid = lane >> 2;
    const int q   = lane & 3;
    const int jg  = wn * 16 + q * 4;    // this thread's hd base (4 contiguous)

    const int a_row_lane = ((lane >> 3) & 1) * 8 + (lane & 7);
    const int a_kadd     = (lane >> 4) * 8;
    const int b_row_lane = (lane >> 4) * 8 + (lane & 7);
    const int b_kadd     = ((lane >> 3) & 1) * 8;

    const int head  = blockIdx.y;
    const int node0 = blockIdx.x * NB;

    // per-thread staging chunk coords (2 chunks of 16B in the x-region)
    const int stg_n0 = tid >> 3;
    const int stg_k0 = (tid & 7) * 8;
    const int stg_n1 = (tid + THREADS) >> 3;
    const int stg_k1 = stg_k0;

    float c_reg[2][2][4];   // [mtile][rowhalf][joff]

    for (int l = 0; l < 2; ++l) {
        // ======== layer prologue ========
        const float* Wih_g = W_ih + (size_t)(l * N_HEADS + head) * (G_DIM * H_DIM);
        const float* Whh_g = W_hh + (size_t)(l * N_HEADS + head) * (G_DIM * H_DIM);

        // B tile, gate-interleave row permutation
        #pragma unroll 1
        for (int i = 0; i < 16; ++i) {
            int gidx = tid + i * THREADS;
            int row_out = gidx >> 4;
            int k8 = (gidx & 15) * 8;
            int tt = (row_out >> 3) & 7;
            int qq = (row_out >> 1) & 3;
            int bb = row_out & 1;
            int wnn = row_out >> 6;
            int g  = ((tt & 1) << 1) | bb;
            int jj = (wnn << 4) | (qq << 2) | (tt >> 1);
            const float* src = (k8 < 64) ? (Wih_g + (g * 64 + jj) * 64 + k8)
                                         : (Whh_g + (g * 64 + jj) * 64 + (k8 - 64));
            float v[8];
            float4 v0 = *(const float4*)(src);
            float4 v1 = *(const float4*)(src + 4);
            v[0]=v0.x; v[1]=v0.y; v[2]=v0.z; v[3]=v0.w;
            v[4]=v1.x; v[5]=v1.y; v[6]=v1.z; v[7]=v1.w;
            cvt8_store_f16(v, smem, SB, swzoff(32, row_out, k8));
        }
        // bias
        {
            const float* bi = b_ih + (size_t)(l * N_HEADS + head) * G_DIM;
            const float* bh = b_hh + (size_t)(l * N_HEADS + head) * G_DIM;
            sbias[tid] = bi[tid] + bh[tid];
        }
        // h0 -> A[0] h-region (k 64..127), fp32 -> fp16
        {
            const float* hsrc = h0 + ((size_t)(head * 2 + l) * N_NODES + node0) * H_DIM;
            #pragma unroll
            for (int i = 0; i < 2; ++i) {
                int gidx = tid + i * THREADS;
                int n  = gidx >> 3;
                int k8 = (gidx & 7) * 8;
                float v[8];
                float4 v0 = *(const float4*)(hsrc + n * 64 + k8);
                float4 v1 = *(const float4*)(hsrc + n * 64 + k8 + 4);
                v[0]=v0.x; v[1]=v0.y; v[2]=v0.z; v[3]=v0.w;
                v[4]=v1.x; v[5]=v1.y; v[6]=v1.z; v[7]=v1.w;
                cvt8_store_f16(v, smem, SA0, swzoff(8, n, 64 + k8));
            }
        }
        // c0 -> registers
        {
            const float* cbase = c0 + ((size_t)(head * 2 + l) * N_NODES + node0) * H_DIM;
            #pragma unroll
            for (int mt = 0; mt < 2; ++mt)
                #pragma unroll
                for (int rh = 0; rh < 2; ++rh) {
                    int rowL = mrow0 + mt * 16 + gid + rh * 8;
                    float4 v = *(const float4*)(cbase + (size_t)rowL * 64 + jg);
                    c_reg[mt][rh][0]=v.x; c_reg[mt][rh][1]=v.y;
                    c_reg[mt][rh][2]=v.z; c_reg[mt][rh][3]=v.w;
                }
        }
        // fp16 input stream for this layer
        const __half* in16 = (l == 0)
            ? (g_x16 + (size_t)node0 * H_DIM)
            : (g_hs0 + ((size_t)head * T_LEN * N_NODES + node0) * H_DIM);
        __half* out_base = ((l == 0) ? g_hs0 : g_hs1)
                         + (size_t)head * T_LEN * N_NODES * H_DIM;

        // x_0 -> A[0] x-region via cp.async
        CP_ASYNC16(sbase + SA0 + swzoff(8, stg_n0, stg_k0), in16 + stg_n0 * 64 + stg_k0);
        CP_ASYNC16(sbase + SA0 + swzoff(8, stg_n1, stg_k1), in16 + stg_n1 * 64 + stg_k1);
        CP_COMMIT(); CP_WAIT0();
        __syncthreads();

        // hoist Whh B-fragments (kc = 6..7) into registers for the whole scan
        uint32_t bfr[2][4][4];
        #pragma unroll
        for (int kh = 0; kh < 2; ++kh)
            #pragma unroll
            for (int nt2 = 0; nt2 < 4; ++nt2) {
                uint32_t off = swzoff(32, nbase + nt2 * 16 + b_row_lane,
                                      (6 + kh) * 16 + b_kadd);
                ldsm4(bfr[kh][nt2], sbase + SB + off);
            }

        // ======== scan (double-buffered A, ONE sync per step) ========
        for (int t = 0; t < T_LEN; ++t) {
            const int SAc = (t & 1) ? SA1 : SA0;
            const int SAn = (t & 1) ? SA0 : SA1;
            const bool notlast = (t + 1 < T_LEN);

            // stage x_{t+1} into A[nxt] x-region via cp.async (overlaps MMA)
            if (notlast) {
                const __half* srcn = in16 + (size_t)(t + 1) * N_NODES * H_DIM;
                CP_ASYNC16(sbase + SAn + swzoff(8, stg_n0, stg_k0), srcn + stg_n0 * 64 + stg_k0);
                CP_ASYNC16(sbase + SAn + swzoff(8, stg_n1, stg_k1), srcn + stg_n1 * 64 + stg_k1);
                CP_COMMIT();
            }

            // accum, bias-initialized
            float acc[2][8][4];
            #pragma unroll
            for (int nt = 0; nt < 8; ++nt) {
                float bv0 = sbias[(((nt & 1) << 1) | 0) * 64 + jg + (nt >> 1)];
                float bv1 = sbias[(((nt & 1) << 1) | 1) * 64 + jg + (nt >> 1)];
                #pragma unroll
                for (int mt = 0; mt < 2; ++mt) {
                    acc[mt][nt][0] = bv0; acc[mt][nt][1] = bv1;
                    acc[mt][nt][2] = bv0; acc[mt][nt][3] = bv1;
                }
            }

            // MMA part 1: kc 0..5 with B from SMEM
            #pragma unroll
            for (int kc = 0; kc < 6; ++kc) {
                int k0 = kc * 16;
                uint32_t af[2][4];
                #pragma unroll
                for (int mt = 0; mt < 2; ++mt) {
                    uint32_t off = swzoff(8, mrow0 + mt * 16 + a_row_lane, k0 + a_kadd);
                    ldsm4(af[mt], sbase + SAc + off);
                }
                #pragma unroll
                for (int nt2 = 0; nt2 < 4; ++nt2) {
                    uint32_t off = swzoff(32, nbase + nt2 * 16 + b_row_lane, k0 + b_kadd);
                    uint32_t bh[4];
                    ldsm4(bh, sbase + SB + off);
                    #pragma unroll
                    for (int hf = 0; hf < 2; ++hf)
                        #pragma unroll
                        for (int mt = 0; mt < 2; ++mt)
                            mma_f16(acc[mt][nt2 * 2 + hf], af[mt], bh[hf*2], bh[hf*2+1]);
                }
            }
            // MMA part 2: kc 6..7 with hoisted B fragments
            #pragma unroll
            for (int kh = 0; kh < 2; ++kh) {
                int k0 = (6 + kh) * 16;
                uint32_t af[2][4];
                #pragma unroll
                for (int mt = 0; mt < 2; ++mt) {
                    uint32_t off = swzoff(8, mrow0 + mt * 16 + a_row_lane, k0 + a_kadd);
                    ldsm4(af[mt], sbase + SAc + off);
                }
                #pragma unroll
                for (int nt2 = 0; nt2 < 4; ++nt2)
                    #pragma unroll
                    for (int hf = 0; hf < 2; ++hf)
                        #pragma unroll
                        for (int mt = 0; mt < 2; ++mt)
                            mma_f16(acc[mt][nt2 * 2 + hf], af[mt],
                                    bfr[kh][nt2][hf*2], bfr[kh][nt2][hf*2+1]);
            }

            // epilogue: cell update; h -> GMEM (+ A[nxt] h-region unless last step)
            #pragma unroll
            for (int mt = 0; mt < 2; ++mt)
                #pragma unroll
                for (int rh = 0; rh < 2; ++rh) {
                    int rowL = mrow0 + mt * 16 + gid + rh * 8;
                    float iv[4], fv[4], gv[4], ov[4];
                    #pragma unroll
                    for (int jo = 0; jo < 4; ++jo) {
                        iv[jo] = acc[mt][2*jo  ][rh*2 + 0];
                        fv[jo] = acc[mt][2*jo  ][rh*2 + 1];
                        gv[jo] = acc[mt][2*jo+1][rh*2 + 0];
                        ov[jo] = acc[mt][2*jo+1][rh*2 + 1];
                    }
                    float2 tg01 = tanh2(gv[0], gv[1]);
                    float2 tg23 = tanh2(gv[2], gv[3]);
                    float tg[4] = {tg01.x, tg01.y, tg23.x, tg23.y};
                    float2 si01 = sig2(iv[0], iv[1]);
                    float2 si23 = sig2(iv[2], iv[3]);
                    float si[4] = {si01.x, si01.y, si23.x, si23.y};
                    float cc[4];
                    #pragma unroll
                    for (int jo = 0; jo < 4; ++jo) {
                        cc[jo] = siga(fv[jo]) * c_reg[mt][rh][jo] + si[jo] * tg[jo];
                        c_reg[mt][rh][jo] = cc[jo];
                    }
                    float2 tc01 = tanh2(cc[0], cc[1]);
                    float2 tc23 = tanh2(cc[2], cc[3]);
                    float tc[4] = {tc01.x, tc01.y, tc23.x, tc23.y};
                    float2 so01 = sig2(ov[0], ov[1]);
                    float2 so23 = sig2(ov[2], ov[3]);
                    float so[4] = {so01.x, so01.y, so23.x, so23.y};
                    float hv[4];
                    #pragma unroll
                    for (int jo = 0; jo < 4; ++jo)
                        hv[jo] = so[jo] * tc[jo];

                    __half2 h0p = __floats2half2_rn(hv[0], hv[1]);
                    __half2 h1p = __floats2half2_rn(hv[2], hv[3]);
                    uint2 hp = make_uint2(*(uint32_t*)&h0p, *(uint32_t*)&h1p);
                    *(uint2*)(out_base + ((size_t)t * N_NODES + node0 + rowL) * H_DIM + jg) = hp;
                    if (notlast)
                        *(uint2*)(smem + SAn + swzoff(8, rowL, 64 + jg)) = hp;
                }
            if (notlast) { CP_WAIT0(); }
            __syncthreads();
        }
        __threadfence();   // layer-0 h STGs visible before layer-1 cp.async reads
        __syncthreads();
    }
}

// out[o][n][hd] = sum_c hs1[c][n][hd] * conv_w[o][c] + conv_b[o]
__global__ __launch_bounds__(256)
void conv_kernel(const float* __restrict__ conv_w,
                 const float* __restrict__ conv_b,
                 float* __restrict__ out)
{
    __shared__ float sw[T_LEN * N_HEADS * T_LEN];
    __shared__ float sb[T_LEN];
    for (int i = threadIdx.x; i < T_LEN * N_HEADS * T_LEN; i += 256)
        sw[i] = conv_w[i];
    if (threadIdx.x < T_LEN) sb[threadIdx.x] = conv_b[threadIdx.x];
    __syncthreads();

    const size_t stride = (size_t)N_NODES * H_DIM;
    size_t nh4 = ((size_t)blockIdx.x * 256 + threadIdx.x) * 4;

    float acc[T_LEN][4];
    #pragma unroll
    for (int o = 0; o < T_LEN; ++o) {
        float b = sb[o];
        acc[o][0] = b; acc[o][1] = b; acc[o][2] = b; acc[o][3] = b;
    }
    #pragma unroll 4
    for (int c = 0; c < N_HEADS * T_LEN; ++c) {
        uint2 raw = *(const uint2*)(g_hs1 + (size_t)c * stride + nh4);
        float2 f0 = __half22float2(*(__half2*)&raw.x);
        float2 f1 = __half22float2(*(__half2*)&raw.y);
        #pragma unroll
        for (int o = 0; o < T_LEN; ++o) {
            float w = sw[o * (N_HEADS * T_LEN) + c];
            acc[o][0] += f0.x * w; acc[o][1] += f0.y * w;
            acc[o][2] += f1.x * w; acc[o][3] += f1.y * w;
        }
    }
    #pragma unroll
    for (int o = 0; o < T_LEN; ++o)
        *(float4*)(out + (size_t)o * stride + nh4) =
            make_float4(acc[o][0], acc[o][1], acc[o][2], acc[o][3]);
}

extern "C" void kernel_launch(void* const* d_in, const int* in_sizes, int n_in,
                              void* d_out, int out_size)
{
    const float* x      = (const float*)d_in[0];
    const float* W_ih   = (const float*)d_in[1];
    const float* W_hh   = (const float*)d_in[2];
    const float* b_ih   = (const float*)d_in[3];
    const float* b_hh   = (const float*)d_in[4];
    const float* h0     = (const float*)d_in[5];
    const float* c0     = (const float*)d_in[6];
    const float* conv_w = (const float*)d_in[7];
    const float* conv_b = (const float*)d_in[8];
    float* out = (float*)d_out;

    cudaFuncSetAttribute(lstm_mma_kernel,
                         cudaFuncAttributeMaxDynamicSharedMemorySize, SMEM_TOTAL);

    // x fp32 -> fp16
    x_convert_kernel<<<(T_LEN * N_NODES * H_DIM) / (8 * 256), 256>>>(x);

    dim3 grid(N_NODES / NB, N_HEADS);     // 256 x 8 = 2048 CTAs
    lstm_mma_kernel<<<grid, THREADS, SMEM_TOTAL>>>(W_ih, W_hh, b_ih, b_hh, h0, c0);

    conv_kernel<<<(N_NODES * H_DIM) / (4 * 256), 256>>>(conv_w, conv_b, out);
}

// round 17
// speedup vs baseline: 2.5924x; 1.0738x over previous
#include <cuda_runtime.h>
#include <cuda_fp16.h>
#include <cstdint>

#define T_LEN   12
#define N_HEADS 8
#define N_NODES 16384
#define H_DIM   64
#define G_DIM   256
#define NB      64           // nodes per CTA (= GEMM M)
#define THREADS 256

// ---- LSTM shared memory layout (bytes) ----
#define SA0     0            // A tile buf0: [64 rows][128 k] fp16 swizzled (16384)
#define SA1     16384        // A tile buf1                                  (16384)
#define SB      32768        // B tile: [256 rows][128 k] fp16              (65536)
#define SBIAS   98304        // bias fp32 [256]                             (1024)
#define SMEM_TOTAL 99328

// Scratch
__device__ __half g_x16[(size_t)T_LEN * N_NODES * H_DIM];            // x in fp16
__device__ __half g_hs0[(size_t)N_HEADS * T_LEN * N_NODES * H_DIM];  // layer-0 h
__device__ __half g_hs1[(size_t)N_HEADS * T_LEN * N_NODES * H_DIM];  // layer-1 h

__device__ __forceinline__ uint32_t swzoff(int R8, int row, int k) {
    uint32_t off = (uint32_t)((((row >> 3) + (k >> 6) * R8) << 10)
                 + ((row & 7) << 7) + ((k & 63) << 1));
    return off ^ ((off >> 3) & 0x70);
}

__device__ __forceinline__ uint32_t smem_u32(const void* p) {
    uint32_t a;
    asm("{ .reg .u64 t; cvta.to.shared.u64 t, %1; cvt.u32.u64 %0, t; }" : "=r"(a) : "l"(p));
    return a;
}

__device__ __forceinline__ void ldsm4(uint32_t* r, uint32_t addr) {
    asm volatile("ldmatrix.sync.aligned.m8n8.x4.shared.b16 {%0,%1,%2,%3}, [%4];"
        : "=r"(r[0]), "=r"(r[1]), "=r"(r[2]), "=r"(r[3]) : "r"(addr));
}

// fp16-accumulator MMA: D(4xh16 in 2 regs) = A*B + C
__device__ __forceinline__ void mma_f16a(uint32_t* c, const uint32_t* a,
                                         uint32_t b0, uint32_t b1) {
    asm volatile("mma.sync.aligned.m16n8k16.row.col.f16.f16.f16.f16 "
        "{%0,%1}, {%2,%3,%4,%5}, {%6,%7}, {%0,%1};"
        : "+r"(c[0]), "+r"(c[1])
        : "r"(a[0]), "r"(a[1]), "r"(a[2]), "r"(a[3]), "r"(b0), "r"(b1));
}

__device__ __forceinline__ float tanha(float x) {
    float y;
    asm("tanh.approx.f32 %0, %1;" : "=f"(y) : "f"(x));
    return y;
}
__device__ __forceinline__ float siga(float x) {
    return fmaf(tanha(0.5f * x), 0.5f, 0.5f);
}
__device__ __forceinline__ float2 tanh2(float a, float b) {
    __half2 hx = __floats2half2_rn(a, b);
    uint32_t xr = *(uint32_t*)&hx, yr;
    asm("tanh.approx.f16x2 %0, %1;" : "=r"(yr) : "r"(xr));
    return __half22float2(*(__half2*)&yr);
}
__device__ __forceinline__ float2 sig2(float a, float b) {
    float2 t = tanh2(0.5f * a, 0.5f * b);
    return make_float2(fmaf(t.x, 0.5f, 0.5f), fmaf(t.y, 0.5f, 0.5f));
}

#define CP_ASYNC16(dst_u32, src) \
    asm volatile("cp.async.ca.shared.global [%0], [%1], 16;" :: "r"(dst_u32), "l"(src) : "memory")
#define CP_COMMIT() asm volatile("cp.async.commit_group;" ::: "memory")
#define CP_WAIT0()  asm volatile("cp.async.wait_group 0;" ::: "memory")

// 8 fp32 -> 8 fp16, one 16B store into swizzled tile
__device__ __forceinline__ void cvt8_store_f16(const float* v, char* smem,
                                               int tile, uint32_t off) {
    uint32_t w[4];
    #pragma unroll
    for (int qq = 0; qq < 4; ++qq) {
        __half2 h = __floats2half2_rn(v[2 * qq], v[2 * qq + 1]);
        w[qq] = *(uint32_t*)&h;
    }
    *(uint4*)(smem + tile + off) = make_uint4(w[0], w[1], w[2], w[3]);
}

// x fp32 -> fp16 (one-time)
__global__ __launch_bounds__(256)
void x_convert_kernel(const float* __restrict__ x)
{
    size_t i8 = ((size_t)blockIdx.x * 256 + threadIdx.x) * 8;
    float4 v0 = *(const float4*)(x + i8);
    float4 v1 = *(const float4*)(x + i8 + 4);
    __half2 h0 = __floats2half2_rn(v0.x, v0.y);
    __half2 h1 = __floats2half2_rn(v0.z, v0.w);
    __half2 h2 = __floats2half2_rn(v1.x, v1.y);
    __half2 h3 = __floats2half2_rn(v1.z, v1.w);
    *(uint4*)(g_x16 + i8) = make_uint4(*(uint32_t*)&h0, *(uint32_t*)&h1,
                                       *(uint32_t*)&h2, *(uint32_t*)&h3);
}

__global__ __launch_bounds__(THREADS, 2)
void lstm_mma_kernel(const float* __restrict__ W_ih,
                     const float* __restrict__ W_hh,
                     const float* __restrict__ b_ih,
                     const float* __restrict__ b_hh,
                     const float* __restrict__ h0,
                     const float* __restrict__ c0)
{
    extern __shared__ char smem[];
    const uint32_t sbase = smem_u32(smem);
    float* sbias = (float*)(smem + SBIAS);

    const int tid  = threadIdx.x;
    const int warp = tid >> 5;
    const int lane = tid & 31;
    const int wm = warp & 1;            // M-warp (2)
    const int wn = warp >> 1;           // N-warp (4)
    const int mrow0 = wm * 32;
    const int nbase = wn * 64;          // permuted-B row base
    const int gid = lane >> 2;
    const int q   = lane & 3;
    const int jg  = wn * 16 + q * 4;    // this thread's hd base (4 contiguous)

    const int a_row_lane = ((lane >> 3) & 1) * 8 + (lane & 7);
    const int a_kadd     = (lane >> 4) * 8;
    const int b_row_lane = (lane >> 4) * 8 + (lane & 7);
    const int b_kadd     = ((lane >> 3) & 1) * 8;

    const int head  = blockIdx.y;
    const int node0 = blockIdx.x * NB;

    // per-thread staging chunk coords (2 chunks of 16B in the x-region)
    const int stg_n0 = tid >> 3;
    const int stg_k0 = (tid & 7) * 8;
    const int stg_n1 = (tid + THREADS) >> 3;
    const int stg_k1 = stg_k0;

    float c_reg[2][2][4];   // [mtile][rowhalf][joff]

    for (int l = 0; l < 2; ++l) {
        // ======== layer prologue ========
        const float* Wih_g = W_ih + (size_t)(l * N_HEADS + head) * (G_DIM * H_DIM);
        const float* Whh_g = W_hh + (size_t)(l * N_HEADS + head) * (G_DIM * H_DIM);

        // B tile, gate-interleave row permutation
        #pragma unroll 1
        for (int i = 0; i < 16; ++i) {
            int gidx = tid + i * THREADS;
            int row_out = gidx >> 4;
            int k8 = (gidx & 15) * 8;
            int tt = (row_out >> 3) & 7;
            int qq = (row_out >> 1) & 3;
            int bb = row_out & 1;
            int wnn = row_out >> 6;
            int g  = ((tt & 1) << 1) | bb;
            int jj = (wnn << 4) | (qq << 2) | (tt >> 1);
            const float* src = (k8 < 64) ? (Wih_g + (g * 64 + jj) * 64 + k8)
                                         : (Whh_g + (g * 64 + jj) * 64 + (k8 - 64));
            float v[8];
            float4 v0 = *(const float4*)(src);
            float4 v1 = *(const float4*)(src + 4);
            v[0]=v0.x; v[1]=v0.y; v[2]=v0.z; v[3]=v0.w;
            v[4]=v1.x; v[5]=v1.y; v[6]=v1.z; v[7]=v1.w;
            cvt8_store_f16(v, smem, SB, swzoff(32, row_out, k8));
        }
        // bias
        {
            const float* bi = b_ih + (size_t)(l * N_HEADS + head) * G_DIM;
            const float* bh = b_hh + (size_t)(l * N_HEADS + head) * G_DIM;
            sbias[tid] = bi[tid] + bh[tid];
        }
        // h0 -> A[0] h-region (k 64..127), fp32 -> fp16
        {
            const float* hsrc = h0 + ((size_t)(head * 2 + l) * N_NODES + node0) * H_DIM;
            #pragma unroll
            for (int i = 0; i < 2; ++i) {
                int gidx = tid + i * THREADS;
                int n  = gidx >> 3;
                int k8 = (gidx & 7) * 8;
                float v[8];
                float4 v0 = *(const float4*)(hsrc + n * 64 + k8);
                float4 v1 = *(const float4*)(hsrc + n * 64 + k8 + 4);
                v[0]=v0.x; v[1]=v0.y; v[2]=v0.z; v[3]=v0.w;
                v[4]=v1.x; v[5]=v1.y; v[6]=v1.z; v[7]=v1.w;
                cvt8_store_f16(v, smem, SA0, swzoff(8, n, 64 + k8));
            }
        }
        // c0 -> registers
        {
            const float* cbase = c0 + ((size_t)(head * 2 + l) * N_NODES + node0) * H_DIM;
            #pragma unroll
            for (int mt = 0; mt < 2; ++mt)
                #pragma unroll
                for (int rh = 0; rh < 2; ++rh) {
                    int rowL = mrow0 + mt * 16 + gid + rh * 8;
                    float4 v = *(const float4*)(cbase + (size_t)rowL * 64 + jg);
                    c_reg[mt][rh][0]=v.x; c_reg[mt][rh][1]=v.y;
                    c_reg[mt][rh][2]=v.z; c_reg[mt][rh][3]=v.w;
                }
        }
        // fp16 input stream for this layer
        const __half* in16 = (l == 0)
            ? (g_x16 + (size_t)node0 * H_DIM)
            : (g_hs0 + ((size_t)head * T_LEN * N_NODES + node0) * H_DIM);
        __half* out_base = ((l == 0) ? g_hs0 : g_hs1)
                         + (size_t)head * T_LEN * N_NODES * H_DIM;

        // x_0 -> A[0] x-region via cp.async
        CP_ASYNC16(sbase + SA0 + swzoff(8, stg_n0, stg_k0), in16 + stg_n0 * 64 + stg_k0);
        CP_ASYNC16(sbase + SA0 + swzoff(8, stg_n1, stg_k1), in16 + stg_n1 * 64 + stg_k1);
        CP_COMMIT(); CP_WAIT0();
        __syncthreads();

        // hoist Whh B-fragments (kc = 6..7) into registers for the whole scan
        uint32_t bfr[2][4][4];
        #pragma unroll
        for (int kh = 0; kh < 2; ++kh)
            #pragma unroll
            for (int nt2 = 0; nt2 < 4; ++nt2) {
                uint32_t off = swzoff(32, nbase + nt2 * 16 + b_row_lane,
                                      (6 + kh) * 16 + b_kadd);
                ldsm4(bfr[kh][nt2], sbase + SB + off);
            }
        // bias as packed half2 per nt column-pair: (bv0, bv1)
        uint32_t bias2[8];
        #pragma unroll
        for (int nt = 0; nt < 8; ++nt) {
            float bv0 = sbias[(((nt & 1) << 1) | 0) * 64 + jg + (nt >> 1)];
            float bv1 = sbias[(((nt & 1) << 1) | 1) * 64 + jg + (nt >> 1)];
            __half2 b2 = __floats2half2_rn(bv0, bv1);
            bias2[nt] = *(uint32_t*)&b2;
        }

        // ======== scan (double-buffered A, ONE sync per step) ========
        for (int t = 0; t < T_LEN; ++t) {
            const int SAc = (t & 1) ? SA1 : SA0;
            const int SAn = (t & 1) ? SA0 : SA1;
            const bool notlast = (t + 1 < T_LEN);

            // stage x_{t+1} into A[nxt] x-region via cp.async (overlaps MMA)
            if (notlast) {
                const __half* srcn = in16 + (size_t)(t + 1) * N_NODES * H_DIM;
                CP_ASYNC16(sbase + SAn + swzoff(8, stg_n0, stg_k0), srcn + stg_n0 * 64 + stg_k0);
                CP_ASYNC16(sbase + SAn + swzoff(8, stg_n1, stg_k1), srcn + stg_n1 * 64 + stg_k1);
                CP_COMMIT();
            }

            // accum (fp16 pairs), bias-initialized; acc[mt][nt][rh]
            uint32_t acc[2][8][2];
            #pragma unroll
            for (int nt = 0; nt < 8; ++nt)
                #pragma unroll
                for (int mt = 0; mt < 2; ++mt) {
                    acc[mt][nt][0] = bias2[nt];
                    acc[mt][nt][1] = bias2[nt];
                }

            // MMA part 1: kc 0..5 with B from SMEM
            #pragma unroll
            for (int kc = 0; kc < 6; ++kc) {
                int k0 = kc * 16;
                uint32_t af[2][4];
                #pragma unroll
                for (int mt = 0; mt < 2; ++mt) {
                    uint32_t off = swzoff(8, mrow0 + mt * 16 + a_row_lane, k0 + a_kadd);
                    ldsm4(af[mt], sbase + SAc + off);
                }
                #pragma unroll
                for (int nt2 = 0; nt2 < 4; ++nt2) {
                    uint32_t off = swzoff(32, nbase + nt2 * 16 + b_row_lane, k0 + b_kadd);
                    uint32_t bh[4];
                    ldsm4(bh, sbase + SB + off);
                    #pragma unroll
                    for (int hf = 0; hf < 2; ++hf)
                        #pragma unroll
                        for (int mt = 0; mt < 2; ++mt)
                            mma_f16a(acc[mt][nt2 * 2 + hf], af[mt], bh[hf*2], bh[hf*2+1]);
                }
            }
            // MMA part 2: kc 6..7 with hoisted B fragments
            #pragma unroll
            for (int kh = 0; kh < 2; ++kh) {
                int k0 = (6 + kh) * 16;
                uint32_t af[2][4];
                #pragma unroll
                for (int mt = 0; mt < 2; ++mt) {
                    uint32_t off = swzoff(8, mrow0 + mt * 16 + a_row_lane, k0 + a_kadd);
                    ldsm4(af[mt], sbase + SAc + off);
                }
                #pragma unroll
                for (int nt2 = 0; nt2 < 4; ++nt2)
                    #pragma unroll
                    for (int hf = 0; hf < 2; ++hf)
                        #pragma unroll
                        for (int mt = 0; mt < 2; ++mt)
                            mma_f16a(acc[mt][nt2 * 2 + hf], af[mt],
                                     bfr[kh][nt2][hf*2], bfr[kh][nt2][hf*2+1]);
            }

            // epilogue: cell update; h -> GMEM (+ A[nxt] h-region unless last step)
            #pragma unroll
            for (int mt = 0; mt < 2; ++mt)
                #pragma unroll
                for (int rh = 0; rh < 2; ++rh) {
                    int rowL = mrow0 + mt * 16 + gid + rh * 8;
                    float iv[4], fv[4], gv[4], ov[4];
                    #pragma unroll
                    for (int jo = 0; jo < 4; ++jo) {
                        float2 ifp = __half22float2(*(__half2*)&acc[mt][2*jo  ][rh]);
                        float2 gop = __half22float2(*(__half2*)&acc[mt][2*jo+1][rh]);
                        iv[jo] = ifp.x; fv[jo] = ifp.y;
                        gv[jo] = gop.x; ov[jo] = gop.y;
                    }
                    float2 tg01 = tanh2(gv[0], gv[1]);
                    float2 tg23 = tanh2(gv[2], gv[3]);
                    float tg[4] = {tg01.x, tg01.y, tg23.x, tg23.y};
                    float2 si01 = sig2(iv[0], iv[1]);
                    float2 si23 = sig2(iv[2], iv[3]);
                    float si[4] = {si01.x, si01.y, si23.x, si23.y};
                    float cc[4];
                    #pragma unroll
                    for (int jo = 0; jo < 4; ++jo) {
                        cc[jo] = siga(fv[jo]) * c_reg[mt][rh][jo] + si[jo] * tg[jo];
                        c_reg[mt][rh][jo] = cc[jo];
                    }
                    float2 tc01 = tanh2(cc[0], cc[1]);
                    float2 tc23 = tanh2(cc[2], cc[3]);
                    float tc[4] = {tc01.x, tc01.y, tc23.x, tc23.y};
                    float2 so01 = sig2(ov[0], ov[1]);
                    float2 so23 = sig2(ov[2], ov[3]);
                    float so[4] = {so01.x, so01.y, so23.x, so23.y};
                    float hv[4];
                    #pragma unroll
                    for (int jo = 0; jo < 4; ++jo)
                        hv[jo] = so[jo] * tc[jo];

                    __half2 h0p = __floats2half2_rn(hv[0], hv[1]);
                    __half2 h1p = __floats2half2_rn(hv[2], hv[3]);
                    uint2 hp = make_uint2(*(uint32_t*)&h0p, *(uint32_t*)&h1p);
                    *(uint2*)(out_base + ((size_t)t * N_NODES + node0 + rowL) * H_DIM + jg) = hp;
                    if (notlast)
                        *(uint2*)(smem + SAn + swzoff(8, rowL, 64 + jg)) = hp;
                }
            if (notlast) { CP_WAIT0(); }
            __syncthreads();
        }
        __threadfence();   // layer-0 h STGs visible before layer-1 cp.async reads
        __syncthreads();
    }
}

// out[o][n][hd] = sum_c hs1[c][n][hd] * conv_w[o][c] + conv_b[o]
__global__ __launch_bounds__(256)
void conv_kernel(const float* __restrict__ conv_w,
                 const float* __restrict__ conv_b,
                 float* __restrict__ out)
{
    __shared__ float sw[T_LEN * N_HEADS * T_LEN];
    __shared__ float sb[T_LEN];
    for (int i = threadIdx.x; i < T_LEN * N_HEADS * T_LEN; i += 256)
        sw[i] = conv_w[i];
    if (threadIdx.x < T_LEN) sb[threadIdx.x] = conv_b[threadIdx.x];
    __syncthreads();

    const size_t stride = (size_t)N_NODES * H_DIM;
    size_t nh4 = ((size_t)blockIdx.x * 256 + threadIdx.x) * 4;

    float acc[T_LEN][4];
    #pragma unroll
    for (int o = 0; o < T_LEN; ++o) {
        float b = sb[o];
        acc[o][0] = b; acc[o][1] = b; acc[o][2] = b; acc[o][3] = b;
    }
    #pragma unroll 4
    for (int c = 0; c < N_HEADS * T_LEN; ++c) {
        uint2 raw = *(const uint2*)(g_hs1 + (size_t)c * stride + nh4);
        float2 f0 = __half22float2(*(__half2*)&raw.x);
        float2 f1 = __half22float2(*(__half2*)&raw.y);
        #pragma unroll
        for (int o = 0; o < T_LEN; ++o) {
            float w = sw[o * (N_HEADS * T_LEN) + c];
            acc[o][0] += f0.x * w; acc[o][1] += f0.y * w;
            acc[o][2] += f1.x * w; acc[o][3] += f1.y * w;
        }
    }
    #pragma unroll
    for (int o = 0; o < T_LEN; ++o)
        *(float4*)(out + (size_t)o * stride + nh4) =
            make_float4(acc[o][0], acc[o][1], acc[o][2], acc[o][3]);
}

extern "C" void kernel_launch(void* const* d_in, const int* in_sizes, int n_in,
                              void* d_out, int out_size)
{
    const float* x      = (const float*)d_in[0];
    const float* W_ih   = (const float*)d_in[1];
    const float* W_hh   = (const float*)d_in[2];
    const float* b_ih   = (const float*)d_in[3];
    const float* b_hh   = (const float*)d_in[4];
    const float* h0     = (const float*)d_in[5];
    const float* c0     = (const float*)d_in[6];
    const float* conv_w = (const float*)d_in[7];
    const float* conv_b = (const float*)d_in[8];
    float* out = (float*)d_out;

    cudaFuncSetAttribute(lstm_mma_kernel,
                         cudaFuncAttributeMaxDynamicSharedMemorySize, SMEM_TOTAL);

    // x fp32 -> fp16
    x_convert_kernel<<<(T_LEN * N_NODES * H_DIM) / (8 * 256), 256>>>(x);

    dim3 grid(N_NODES / NB, N_HEADS);     // 256 x 8 = 2048 CTAs
    lstm_mma_kernel<<<grid, THREADS, SMEM_TOTAL>>>(W_ih, W_hh, b_ih, b_hh, h0, c0);

    conv_kernel<<<(N_NODES * H_DIM) / (4 * 256), 256>>>(conv_w, conv_b, out);
}